// round 15
// baseline (speedup 1.0000x reference)
#include <cuda_runtime.h>
#include <cuda_fp16.h>
#include <math.h>
#include <float.h>
#include <stdint.h>

#define NPTS 2048
#define KNN 64
#define BEFF 4
#define PBIG (KNN*NPTS)   // 131072
#define R2 0.09f

// ------------------------- scratch (device globals; no allocs allowed) -------
__device__ int    g_idx[BEFF*NPTS*KNN];
__device__ __half g_act2h[(size_t)BEFF*256*PBIG];
__device__ float  g_mx[BEFF*192*NPTS];
__device__ float  g_mn[BEFF*192*NPTS];
__device__ float  g_feat[BEFF*192*NPTS];
__device__ float  g_q  [BEFF*64*NPTS];          // padded head dim 48->64
__device__ float  g_qT [BEFF*NPTS*64];
__device__ float  g_v  [BEFF*192*NPTS];
__device__ float  g_att[(size_t)BEFF*NPTS*NPTS];
__device__ float  g_cs4[4*BEFF*NPTS];           // per-attention-block colsums
__device__ float  g_xr [BEFF*192*NPTS];
__device__ float  g_t  [BEFF*192*NPTS];
__device__ float  g_cat[BEFF*768*NPTS];
__device__ float  g_fused[BEFF*768*NPTS];
__device__ double g_sum[2][512];
__device__ double g_gram[BEFF][28];
__device__ float  g_W1f[BEFF*128*8];
__device__ float  g_qkw64[64*192];
__device__ float  g_coefA[BEFF*768];
__device__ float  g_coefB[BEFF*768];

#define OFF_GN2   0
#define OFF_GN3   64
#define OFF_BLK   128
#define OFF_FUSE  384

__device__ __forceinline__ uint32_t f2tf32(float v) {
    uint32_t u;
    asm("cvt.rna.tf32.f32 %0, %1;" : "=r"(u) : "f"(v));
    return u;
}
__device__ __forceinline__ uint32_t packh2(float a, float b) {
    __half2 h = __floats2half2_rn(a, b);
    return *(uint32_t*)&h;
}
__device__ __forceinline__ float4 ld4(const float* p) { return *(const float4*)p; }
__device__ __forceinline__ float4 ld4(const __half* p) {
    uint2 u = *(const uint2*)p;
    __half2 h0 = *(__half2*)&u.x, h1 = *(__half2*)&u.y;
    float2 a = __half22float2(h0), b = __half22float2(h1);
    return make_float4(a.x, a.y, b.x, b.y);
}
__device__ __forceinline__ void st2(__half* p, float a, float b) {
    *(__half2*)p = __floats2half2_rn(a, b);
}

#define MMA_F16(d, a, b0v) \
    asm volatile( \
        "mma.sync.aligned.m16n8k16.row.col.f32.f16.f16.f32 " \
        "{%0,%1,%2,%3}, {%4,%5,%6,%7}, {%8,%9}, {%0,%1,%2,%3};\n" \
        : "+f"(d[0]), "+f"(d[1]), "+f"(d[2]), "+f"(d[3]) \
        : "r"(a.x), "r"(a.y), "r"(a.z), "r"(a.w), "r"(b0v[0]), "r"(b0v[1]))

// ------------------------- ball query ---------------------------------------
__global__ void ballq_kernel(const float* __restrict__ src,
                             const float* __restrict__ tgt,
                             int* __restrict__ idxout)
{
    int b = blockIdx.y;
    const float* xyz = (b < 2) ? src + (size_t)b*NPTS*3 : tgt + (size_t)(b-2)*NPTS*3;
    __shared__ float sx[NPTS], sy[NPTS], sz[NPTS], sq[NPTS];
    for (int i = threadIdx.x; i < NPTS; i += blockDim.x) {
        float x = xyz[i*3], y = xyz[i*3+1], z = xyz[i*3+2];
        sx[i] = x; sy[i] = y; sz[i] = z;
        sq[i] = x*x + y*y + z*z;
    }
    __syncthreads();
    int m = blockIdx.x*blockDim.x + threadIdx.x;
    float qx = sx[m], qy = sy[m], qz = sz[m], qs = sq[m];
    int* o = idxout + ((size_t)b*NPTS + m)*KNN;
    int cnt = 0;
    for (int j = 0; j < NPTS && cnt < KNN; j++) {
        float d = qs + sq[j] - 2.f*(qx*sx[j] + qy*sy[j] + qz*sz[j]);
        if (d <= R2) o[cnt++] = j;
    }
    int f0 = o[0];
    for (; cnt < KNN; cnt++) o[cnt] = f0;
}

// ------------------------- zero (gram + stats arena + colsums) ---------------
__global__ void zero_all_kernel() {
    int t = threadIdx.x;
    for (int i = t; i < 1024; i += 256) ((double*)g_sum)[i] = 0.0;
    if (t < BEFF*28) ((double*)g_gram)[t] = 0.0;
    for (int i = t; i < 4*BEFF*NPTS; i += 256) g_cs4[i] = 0.f;
}

// ------------------------- feature gram (analytic GN1 stats) -----------------
__global__ void gram_kernel(const float* __restrict__ src,
                            const float* __restrict__ tgt,
                            const int* __restrict__ idx)
{
    int b = blockIdx.y;
    const float* xyz = (b < 2) ? src + (size_t)b*NPTS*3 : tgt + (size_t)(b-2)*NPTS*3;
    float acc[27];
    #pragma unroll
    for (int i = 0; i < 27; i++) acc[i] = 0.f;
    for (int pos = blockIdx.x*256 + threadIdx.x; pos < PBIG; pos += 64*256) {
        int n = pos >> 6, k = pos & 63;
        int j = idx[((size_t)b*NPTS + n)*KNN + k];
        float f[6];
        f[0] = xyz[n*3]; f[1] = xyz[n*3+1]; f[2] = xyz[n*3+2];
        f[3] = xyz[j*3]   - f[0];
        f[4] = xyz[j*3+1] - f[1];
        f[5] = xyz[j*3+2] - f[2];
        #pragma unroll
        for (int i = 0; i < 6; i++) acc[i] += f[i];
        int c = 6;
        #pragma unroll
        for (int i = 0; i < 6; i++)
            #pragma unroll
            for (int jj = i; jj < 6; jj++)
                acc[c++] += f[i]*f[jj];
    }
    #pragma unroll
    for (int i = 0; i < 27; i++)
        #pragma unroll
        for (int o = 16; o; o >>= 1)
            acc[i] += __shfl_down_sync(0xFFFFFFFFu, acc[i], o);
    __shared__ float sh[8][27];
    int lane = threadIdx.x & 31, w = threadIdx.x >> 5;
    if (lane == 0)
        #pragma unroll
        for (int i = 0; i < 27; i++) sh[w][i] = acc[i];
    __syncthreads();
    if (threadIdx.x < 27) {
        double s = 0.0;
        for (int ww = 0; ww < 8; ww++) s += (double)sh[ww][threadIdx.x];
        atomicAdd(&g_gram[b][threadIdx.x], s);
    }
}

// ------------------------- coeff1: analytic GN1 -> folded W1f ---------------
__global__ void coeff1_kernel(const float* __restrict__ W1,
                              const float* __restrict__ gnw,
                              const float* __restrict__ gnb,
                              float* __restrict__ W1f)
{
    int b = blockIdx.x, c = threadIdx.x;
    double S[6], G[21];
    #pragma unroll
    for (int i = 0; i < 6; i++) S[i] = g_gram[b][i];
    #pragma unroll
    for (int i = 0; i < 21; i++) G[i] = g_gram[b][6+i];
    float w[6];
    #pragma unroll
    for (int i = 0; i < 6; i++) w[i] = W1[c*6+i];
    double s = 0.0, q = 0.0;
    #pragma unroll
    for (int i = 0; i < 6; i++) s += (double)w[i]*S[i];
    {
        int ci = 0;
        #pragma unroll
        for (int i = 0; i < 6; i++)
            #pragma unroll
            for (int j = i; j < 6; j++, ci++)
                q += (i==j ? 1.0 : 2.0) * (double)w[i]*(double)w[j]*G[ci];
    }
    double ss = s, qq = q;
    #pragma unroll
    for (int o = 16; o; o >>= 1) {
        ss += __shfl_down_sync(0xFFFFFFFFu, ss, o);
        qq += __shfl_down_sync(0xFFFFFFFFu, qq, o);
    }
    ss = __shfl_sync(0xFFFFFFFFu, ss, 0);
    qq = __shfl_sync(0xFFFFFFFFu, qq, 0);
    double count = 32.0 * (double)PBIG;
    double mean = ss / count;
    double var  = qq / count - mean*mean;
    float a  = gnw[c] * (float)(1.0 / sqrt(var + 1e-5));
    float b2 = gnb[c] - (float)mean * a;
    float* dst = W1f + ((size_t)b*128 + c)*8;
    #pragma unroll
    for (int i = 0; i < 6; i++) dst[i] = a*w[i];
    dst[6] = b2; dst[7] = 0.f;
}

// ------------------------- pad qk_w 48x192 -> 64x192 -------------------------
__global__ void pad_qkw_kernel(const float* __restrict__ qkw)
{
    int i = blockIdx.x*256 + threadIdx.x;
    if (i >= 64*192) return;
    int row = i / 192;
    g_qkw64[i] = (row < 48) ? qkw[i] : 0.f;
}

// ------------------------- layer2 fused GEMM (fp16 MMA, BK=32) ---------------
__global__ void __launch_bounds__(256) layer2_kernel(
    const float* __restrict__ W,
    const float* __restrict__ src, const float* __restrict__ tgt,
    const int* __restrict__ idx,
    const float* __restrict__ W1f,
    __half* __restrict__ out)
{
    const int bb = blockIdx.z;
    const int m0 = blockIdx.y * 128;
    const int p0 = blockIdx.x * 128;
    const float* xyz = (bb < 2) ? src + (size_t)bb*NPTS*3 : tgt + (size_t)(bb-2)*NPTS*3;
    __half* Ob = out + (size_t)bb*256*PBIG;

    __shared__ uint32_t sA[2][2048];
    __shared__ uint32_t sB_[2][2176];
    __shared__ float sF[7*132];
    __shared__ float sW1[128*8];
    __shared__ float sS[4], sQ[4];

    const int t = threadIdx.x;
    const int lane = t & 31;
    const int w = t >> 5;
    const int warpM = w >> 2;
    const int warpN = w & 3;
    const int g  = lane >> 2;
    const int tg = lane & 3;

    for (int i = t; i < 128*8; i += 256) sW1[i] = W1f[(size_t)bb*128*8 + i];
    if (t < 128) {
        int col = t;
        int n = (p0 >> 6) + (col >> 6);
        int k = col & 63;
        int j = idx[((size_t)bb*NPTS + n)*KNN + k];
        float cx = xyz[n*3], cy = xyz[n*3+1], cz = xyz[n*3+2];
        sF[0*132+col] = cx; sF[1*132+col] = cy; sF[2*132+col] = cz;
        sF[3*132+col] = xyz[j*3]   - cx;
        sF[4*132+col] = xyz[j*3+1] - cy;
        sF[5*132+col] = xyz[j*3+2] - cz;
        sF[6*132+col] = 1.f;
    }
    if (t < 4) { sS[t] = 0.f; sQ[t] = 0.f; }

    float acc[4][4][4];
    #pragma unroll
    for (int i = 0; i < 4; i++)
        #pragma unroll
        for (int j = 0; j < 4; j++)
            #pragma unroll
            for (int r = 0; r < 4; r++) acc[i][j][r] = 0.f;

    float4 rA[2][2];
    auto loadA = [&](int k0) {
        #pragma unroll
        for (int i = 0; i < 2; i++) {
            int f = t*2 + i;
            int m = f >> 2, kq = f & 3;
            const float* sp = W + (size_t)(m0+m)*128 + k0 + kq*8;
            rA[i][0] = *(const float4*)sp;
            rA[i][1] = *(const float4*)(sp+4);
        }
    };
    auto storeA = [&](int buf) {
        #pragma unroll
        for (int i = 0; i < 2; i++) {
            int f = t*2 + i;
            int m = f >> 2, kq = f & 3;
            float vv[8] = {rA[i][0].x, rA[i][0].y, rA[i][0].z, rA[i][0].w,
                           rA[i][1].x, rA[i][1].y, rA[i][1].z, rA[i][1].w};
            int mf = m >> 4, mm = m & 15;
            int gg = mm & 7, hi = mm >> 3;
            #pragma unroll
            for (int e2 = 0; e2 < 4; e2++) {
                int k = kq*8 + e2*2;
                int kc = k >> 4, kk = k & 15;
                int khi = kk >> 3, tg2 = (kk >> 1) & 3;
                int r = hi + 2*khi;
                sA[buf][((kc*8 + mf)*32 + gg*4 + tg2)*4 + r] = packh2(vv[e2*2], vv[e2*2+1]);
            }
        }
    };
    auto computeB = [&](int k0, int buf) {
        #pragma unroll
        for (int i = 0; i < 2; i++) {
            int f = t + i*256;
            int k2 = f >> 5, pq = f & 31;
            const float* wa = &sW1[(k0 + 2*k2    )*8];
            const float* wb = &sW1[(k0 + 2*k2 + 1)*8];
            uint32_t* dst = &sB_[buf][k2*136 + pq*4];
            #pragma unroll
            for (int e = 0; e < 4; e++) {
                int c4 = pq*4 + e;
                float va = wa[6], vb = wb[6];
                #pragma unroll
                for (int ii = 0; ii < 6; ii++) {
                    float fv = sF[ii*132 + c4];
                    va = fmaf(wa[ii], fv, va);
                    vb = fmaf(wb[ii], fv, vb);
                }
                va = fmaxf(va, 0.f); vb = fmaxf(vb, 0.f);
                dst[e] = packh2(va, vb);
            }
        }
    };
    __syncthreads();

    loadA(0); storeA(0); computeB(0, 0);
    __syncthreads();
    int cur = 0;
    for (int k0 = 0; k0 < 128; k0 += 32) {
        int nk = k0 + 32;
        bool more = nk < 128;
        if (more) loadA(nk);
        #pragma unroll
        for (int kc = 0; kc < 2; kc++) {
            uint4 af[4];
            #pragma unroll
            for (int i = 0; i < 4; i++)
                af[i] = ((const uint4*)sA[cur])[(kc*8 + warpM*4 + i)*32 + lane];
            uint32_t b0[4][2];
            #pragma unroll
            for (int j = 0; j < 4; j++) {
                int col = warpN*32 + j*8 + g;
                b0[j][0] = sB_[cur][(kc*8 + tg  )*136 + col];
                b0[j][1] = sB_[cur][(kc*8 + tg+4)*136 + col];
            }
            #pragma unroll
            for (int i = 0; i < 4; i++)
                #pragma unroll
                for (int j = 0; j < 4; j++)
                    MMA_F16(acc[i][j], af[i], b0[j]);
        }
        if (more) { storeA(cur^1); computeB(nk, cur^1); }
        __syncthreads();
        cur ^= 1;
    }

    float s0 = 0.f, q0 = 0.f, s1 = 0.f, q1 = 0.f;
    #pragma unroll
    for (int i = 0; i < 4; i++) {
        int mlo = m0 + warpM*64 + i*16 + g;
        int mhi = mlo + 8;
        #pragma unroll
        for (int j = 0; j < 4; j++) {
            int p = p0 + warpN*32 + j*8 + 2*tg;
            st2(&Ob[(size_t)mlo*PBIG + p], acc[i][j][0], acc[i][j][1]);
            st2(&Ob[(size_t)mhi*PBIG + p], acc[i][j][2], acc[i][j][3]);
            #pragma unroll
            for (int r = 0; r < 4; r++) {
                float v = acc[i][j][r];
                if (i < 2) { s0 += v; q0 = fmaf(v, v, q0); }
                else       { s1 += v; q1 = fmaf(v, v, q1); }
            }
        }
    }
    const unsigned fm = 0xFFFFFFFFu;
    s0 += __shfl_xor_sync(fm, s0, 1); s0 += __shfl_xor_sync(fm, s0, 2);
    q0 += __shfl_xor_sync(fm, q0, 1); q0 += __shfl_xor_sync(fm, q0, 2);
    s1 += __shfl_xor_sync(fm, s1, 1); s1 += __shfl_xor_sync(fm, s1, 2);
    q1 += __shfl_xor_sync(fm, q1, 1); q1 += __shfl_xor_sync(fm, q1, 2);
    if (tg == 0) {
        atomicAdd(&sS[warpM*2+0], s0); atomicAdd(&sQ[warpM*2+0], q0);
        atomicAdd(&sS[warpM*2+1], s1); atomicAdd(&sQ[warpM*2+1], q1);
    }
    __syncthreads();
    if (t < 4) {
        int bg = OFF_GN2 + bb*8 + m0/32 + t;
        atomicAdd(&g_sum[0][bg], (double)sS[t]);
        atomicAdd(&g_sum[1][bg], (double)sQ[t]);
    }
}

// ------------------------- layer3 fused GEMM (fp16 MMA, 96-row tiles) --------
__global__ void __launch_bounds__(256) layer3_kernel(
    const float* __restrict__ W,
    const __half* __restrict__ act2,
    const float* __restrict__ cA2, const float* __restrict__ cB2,
    float* __restrict__ mxbuf, float* __restrict__ mnbuf)
{
    const int bb = blockIdx.z;
    const int m0 = blockIdx.y * 96;
    const int p0 = blockIdx.x * 128;
    const __half* Bb = act2 + (size_t)bb*256*PBIG;
    const float* cAb = cA2 + bb*256;
    const float* cBb = cB2 + bb*256;

    __shared__ uint32_t sA[2][1536];
    __shared__ uint32_t sB_[2][2176];
    __shared__ float sMx[2][96], sMn[2][96];
    __shared__ float sS[4], sQ[4];

    const int t = threadIdx.x;
    const int lane = t & 31;
    const int w = t >> 5;
    const int warpM = w >> 2;
    const int warpN = w & 3;
    const int g  = lane >> 2;
    const int tg = lane & 3;
    const int nh = warpN >> 1;

    if (t < 4) { sS[t] = 0.f; sQ[t] = 0.f; }

    float acc[3][4][4];
    #pragma unroll
    for (int i = 0; i < 3; i++)
        #pragma unroll
        for (int j = 0; j < 4; j++)
            #pragma unroll
            for (int r = 0; r < 4; r++) acc[i][j][r] = 0.f;

    float4 rA[2][2], rB0[2], rB1[2];
    auto loadAB = [&](int k0) {
        #pragma unroll
        for (int i = 0; i < 2; i++) {
            int f = t*2 + i;
            if (f < 384) {
                int m = f >> 2, kq = f & 3;
                const float* sp = W + (size_t)(m0+m)*256 + k0 + kq*8;
                rA[i][0] = *(const float4*)sp;
                rA[i][1] = *(const float4*)(sp+4);
            }
        }
        #pragma unroll
        for (int i = 0; i < 2; i++) {
            int f = t + i*256;
            int k2 = f >> 5, pq = f & 31;
            rB0[i] = ld4(Bb + (size_t)(k0 + 2*k2    )*PBIG + p0 + pq*4);
            rB1[i] = ld4(Bb + (size_t)(k0 + 2*k2 + 1)*PBIG + p0 + pq*4);
        }
    };
    auto storeAB = [&](int k0, int buf) {
        #pragma unroll
        for (int i = 0; i < 2; i++) {
            int f = t*2 + i;
            if (f < 384) {
                int m = f >> 2, kq = f & 3;
                float vv[8] = {rA[i][0].x, rA[i][0].y, rA[i][0].z, rA[i][0].w,
                               rA[i][1].x, rA[i][1].y, rA[i][1].z, rA[i][1].w};
                int mf = m >> 4, mm = m & 15;
                int gg = mm & 7, hi = mm >> 3;
                #pragma unroll
                for (int e2 = 0; e2 < 4; e2++) {
                    int k = kq*8 + e2*2;
                    int kc = k >> 4, kk = k & 15;
                    int khi = kk >> 3, tg2 = (kk >> 1) & 3;
                    int r = hi + 2*khi;
                    sA[buf][((kc*6 + mf)*32 + gg*4 + tg2)*4 + r] = packh2(vv[e2*2], vv[e2*2+1]);
                }
            }
        }
        #pragma unroll
        for (int i = 0; i < 2; i++) {
            int f = t + i*256;
            int k2 = f >> 5, pq = f & 31;
            int ka = k0 + 2*k2, kb = ka + 1;
            float aa = cAb[ka], ca = cBb[ka];
            float ab = cAb[kb], cb = cBb[kb];
            float va[4] = {rB0[i].x, rB0[i].y, rB0[i].z, rB0[i].w};
            float vb[4] = {rB1[i].x, rB1[i].y, rB1[i].z, rB1[i].w};
            uint32_t* dst = &sB_[buf][k2*136 + pq*4];
            #pragma unroll
            for (int e = 0; e < 4; e++) {
                float x = fmaxf(fmaf(aa, va[e], ca), 0.f);
                float y = fmaxf(fmaf(ab, vb[e], cb), 0.f);
                dst[e] = packh2(x, y);
            }
        }
    };

    loadAB(0); storeAB(0, 0);
    __syncthreads();
    int cur = 0;
    for (int k0 = 0; k0 < 256; k0 += 32) {
        int nk = k0 + 32;
        bool more = nk < 256;
        if (more) loadAB(nk);
        #pragma unroll
        for (int kc = 0; kc < 2; kc++) {
            uint4 af[3];
            #pragma unroll
            for (int i = 0; i < 3; i++)
                af[i] = ((const uint4*)sA[cur])[(kc*6 + warpM*3 + i)*32 + lane];
            uint32_t b0[4][2];
            #pragma unroll
            for (int j = 0; j < 4; j++) {
                int col = warpN*32 + j*8 + g;
                b0[j][0] = sB_[cur][(kc*8 + tg  )*136 + col];
                b0[j][1] = sB_[cur][(kc*8 + tg+4)*136 + col];
            }
            #pragma unroll
            for (int i = 0; i < 3; i++)
                #pragma unroll
                for (int j = 0; j < 4; j++)
                    MMA_F16(acc[i][j], af[i], b0[j]);
        }
        if (more) storeAB(nk, cur^1);
        __syncthreads();
        cur ^= 1;
    }

    const unsigned fm = 0xFFFFFFFFu;
    float sg[3] = {0.f,0.f,0.f}, qg[3] = {0.f,0.f,0.f};
    float rmx[6], rmn[6];
    #pragma unroll
    for (int i = 0; i < 3; i++) {
        int grp = (warpM*3 + i) >> 1;
        #pragma unroll
        for (int lh = 0; lh < 2; lh++) {
            float vmx = -FLT_MAX, vmn = FLT_MAX;
            #pragma unroll
            for (int j = 0; j < 4; j++) {
                float a = acc[i][j][lh*2], b2 = acc[i][j][lh*2+1];
                vmx = fmaxf(vmx, fmaxf(a, b2));
                vmn = fminf(vmn, fminf(a, b2));
                sg[grp] += a + b2;
                qg[grp] += a*a + b2*b2;
            }
            vmx = fmaxf(vmx, __shfl_xor_sync(fm, vmx, 1));
            vmx = fmaxf(vmx, __shfl_xor_sync(fm, vmx, 2));
            vmn = fminf(vmn, __shfl_xor_sync(fm, vmn, 1));
            vmn = fminf(vmn, __shfl_xor_sync(fm, vmn, 2));
            rmx[i*2+lh] = vmx; rmn[i*2+lh] = vmn;
        }
    }
    #pragma unroll
    for (int g2 = 0; g2 < 3; g2++) {
        sg[g2] += __shfl_xor_sync(fm, sg[g2], 1); sg[g2] += __shfl_xor_sync(fm, sg[g2], 2);
        qg[g2] += __shfl_xor_sync(fm, qg[g2], 1); qg[g2] += __shfl_xor_sync(fm, qg[g2], 2);
    }
    if (tg == 0) {
        #pragma unroll
        for (int g2 = 0; g2 < 3; g2++) {
            if (sg[g2] != 0.f || qg[g2] != 0.f) {
                atomicAdd(&sS[g2], sg[g2]); atomicAdd(&sQ[g2], qg[g2]);
            }
        }
        if ((warpN & 1) == 0) {
            #pragma unroll
            for (int i = 0; i < 3; i++)
                #pragma unroll
                for (int lh = 0; lh < 2; lh++) {
                    int mloc = warpM*48 + i*16 + g + lh*8;
                    sMx[nh][mloc] = rmx[i*2+lh];
                    sMn[nh][mloc] = rmn[i*2+lh];
                }
        }
    }
    __syncthreads();
    if (tg == 0 && (warpN & 1) == 1) {
        int n = (p0 >> 6) + nh;
        #pragma unroll
        for (int i = 0; i < 3; i++)
            #pragma unroll
            for (int lh = 0; lh < 2; lh++) {
                int mloc = warpM*48 + i*16 + g + lh*8;
                int m = m0 + mloc;
                float fx = fmaxf(rmx[i*2+lh], sMx[nh][mloc]);
                float fn = fminf(rmn[i*2+lh], sMn[nh][mloc]);
                size_t o = ((size_t)bb*192 + m)*NPTS + n;
                mxbuf[o] = fx; mnbuf[o] = fn;
            }
    }
    if (t < 3) {
        int bg = OFF_GN3 + bb*6 + m0/32 + t;
        atomicAdd(&g_sum[0][bg], (double)sS[t]);
        atomicAdd(&g_sum[1][bg], (double)sQ[t]);
    }
}

// ------------------------- generic fp16 GEMM (BK=32, Kd%32==0) ---------------
// colscale: raw column sums; staging multiplies B by 1/(1e-9+cs) before rounding.
template<int NI>
__global__ void __launch_bounds__(256) gemm_tc_kernel(
    const float* __restrict__ W, long sW,
    const float* __restrict__ B, long sB,
    const float* __restrict__ B2,
    const float* __restrict__ bias,
    const float* __restrict__ colscale,
    float* __restrict__ Out, long sOut,
    float* __restrict__ OutT,
    int M, int Kd, int P, int statG, int statOff)
{
    const int bb = blockIdx.z;
    const int m0 = blockIdx.y * (NI*32);
    const int p0 = blockIdx.x * 128;
    const float* Wb  = W + (size_t)bb*sW;
    const float* Bb  = B + (size_t)bb*sB;
    const float* B2b = B2 ? B2 + (size_t)bb*sB : nullptr;
    float* Ob = Out + (size_t)bb*sOut;

    __shared__ uint32_t sA[2][512*NI];
    __shared__ uint32_t sB_[2][2176];
    __shared__ float sS[4], sQ[4];

    const int t = threadIdx.x;
    const int lane = t & 31;
    const int w = t >> 5;
    const int warpM = w >> 2;
    const int warpN = w & 3;
    const int g  = lane >> 2;
    const int tg = lane & 3;

    if (t < 4) { sS[t] = 0.f; sQ[t] = 0.f; }

    float acc[NI][4][4];
    #pragma unroll
    for (int i = 0; i < NI; i++)
        #pragma unroll
        for (int j = 0; j < 4; j++)
            #pragma unroll
            for (int r = 0; r < 4; r++) acc[i][j][r] = 0.f;

    float4 csv[2];
    #pragma unroll
    for (int i = 0; i < 2; i++) {
        if (colscale) {
            int pq = (t + i*256) & 31;
            float4 c = *(const float4*)(colscale + (size_t)bb*P + p0 + pq*4);
            csv[i] = make_float4(1.f/(1e-9f + c.x), 1.f/(1e-9f + c.y),
                                 1.f/(1e-9f + c.z), 1.f/(1e-9f + c.w));
        } else csv[i] = make_float4(1.f,1.f,1.f,1.f);
    }

    float4 rA[2][2], rB0[2], rB1[2], rC0[2], rC1[2];
    auto loadAB = [&](int k0) {
        #pragma unroll
        for (int i = 0; i < 2; i++) {
            int f = t*2 + i;
            if (f < 128*NI) {
                int m = f >> 2, kq = f & 3;
                int gm = m0 + m;
                if (gm < M) {
                    const float* sp = Wb + (size_t)gm*Kd + k0 + kq*8;
                    rA[i][0] = *(const float4*)sp;
                    rA[i][1] = *(const float4*)(sp+4);
                } else {
                    rA[i][0] = make_float4(0.f,0.f,0.f,0.f);
                    rA[i][1] = make_float4(0.f,0.f,0.f,0.f);
                }
            }
        }
        #pragma unroll
        for (int i = 0; i < 2; i++) {
            int f = t + i*256;
            int pq = f & 31;
            int k2 = f >> 5;
            size_t off0 = (size_t)(k0 + 2*k2)*P + p0 + pq*4;
            rB0[i] = *(const float4*)(Bb + off0);
            rB1[i] = *(const float4*)(Bb + off0 + P);
            if (B2b) {
                rC0[i] = *(const float4*)(B2b + off0);
                rC1[i] = *(const float4*)(B2b + off0 + P);
            }
        }
    };
    auto storeAB = [&](int k0, int buf) {
        #pragma unroll
        for (int i = 0; i < 2; i++) {
            int f = t*2 + i;
            if (f < 128*NI) {
                int m = f >> 2, kq = f & 3;
                int mf = m >> 4, mm = m & 15;
                int gg = mm & 7, hi = mm >> 3;
                float vv[8] = {rA[i][0].x, rA[i][0].y, rA[i][0].z, rA[i][0].w,
                               rA[i][1].x, rA[i][1].y, rA[i][1].z, rA[i][1].w};
                #pragma unroll
                for (int e2 = 0; e2 < 4; e2++) {
                    int k = kq*8 + e2*2;
                    int kc = k >> 4, kk = k & 15;
                    int khi = kk >> 3, tg2 = (kk >> 1) & 3;
                    int r = hi + 2*khi;
                    sA[buf][((kc*(2*NI) + mf)*32 + gg*4 + tg2)*4 + r] =
                        packh2(vv[e2*2], vv[e2*2+1]);
                }
            }
        }
        #pragma unroll
        for (int i = 0; i < 2; i++) {
            int f = t + i*256;
            int pq = f & 31;
            float cs[4] = {csv[i].x, csv[i].y, csv[i].z, csv[i].w};
            int k2 = f >> 5;
            float va[4] = {rB0[i].x, rB0[i].y, rB0[i].z, rB0[i].w};
            float vb[4] = {rB1[i].x, rB1[i].y, rB1[i].z, rB1[i].w};
            if (B2b) {
                va[0] -= rC0[i].x; va[1] -= rC0[i].y; va[2] -= rC0[i].z; va[3] -= rC0[i].w;
                vb[0] -= rC1[i].x; vb[1] -= rC1[i].y; vb[2] -= rC1[i].z; vb[3] -= rC1[i].w;
            }
            uint32_t* dst = &sB_[buf][k2*136 + pq*4];
            #pragma unroll
            for (int e = 0; e < 4; e++)
                dst[e] = packh2(va[e]*cs[e], vb[e]*cs[e]);
        }
    };
    __syncthreads();

    loadAB(0); storeAB(0, 0);
    __syncthreads();
    int cur = 0;
    for (int k0 = 0; k0 < Kd; k0 += 32) {
        int nk = k0 + 32;
        bool more = nk < Kd;
        if (more) loadAB(nk);
        #pragma unroll
        for (int kc = 0; kc < 2; kc++) {
            uint4 af[NI];
            #pragma unroll
            for (int i = 0; i < NI; i++)
                af[i] = ((const uint4*)sA[cur])[(kc*(2*NI) + warpM*NI + i)*32 + lane];
            uint32_t b0[4][2];
            #pragma unroll
            for (int j = 0; j < 4; j++) {
                int col = warpN*32 + j*8 + g;
                b0[j][0] = sB_[cur][(kc*8 + tg  )*136 + col];
                b0[j][1] = sB_[cur][(kc*8 + tg+4)*136 + col];
            }
            #pragma unroll
            for (int i = 0; i < NI; i++)
                #pragma unroll
                for (int j = 0; j < 4; j++)
                    MMA_F16(acc[i][j], af[i], b0[j]);
        }
        if (more) storeAB(nk, cur^1);
        __syncthreads();
        cur ^= 1;
    }

    #pragma unroll
    for (int i = 0; i < NI; i++) {
        int mlo = m0 + warpM*(NI*16) + i*16 + g;
        int mhi = mlo + 8;
        float blo = 0.f, bhi = 0.f;
        if (bias) {
            if (mlo < M) blo = bias[mlo];
            if (mhi < M) bhi = bias[mhi];
        }
        #pragma unroll
        for (int j = 0; j < 4; j++) {
            int p = p0 + warpN*32 + j*8 + 2*tg;
            float v00 = acc[i][j][0] + blo;
            float v01 = acc[i][j][1] + blo;
            float v10 = acc[i][j][2] + bhi;
            float v11 = acc[i][j][3] + bhi;
            if (mlo < M) { Ob[(size_t)mlo*P + p] = v00; Ob[(size_t)mlo*P + p + 1] = v01; }
            if (mhi < M) { Ob[(size_t)mhi*P + p] = v10; Ob[(size_t)mhi*P + p + 1] = v11; }
            if (OutT) {
                float* Tb = OutT + (size_t)bb*P*M;
                if (mlo < M) { Tb[(size_t)p*M + mlo] = v00; Tb[(size_t)(p+1)*M + mlo] = v01; }
                if (mhi < M) { Tb[(size_t)p*M + mhi] = v10; Tb[(size_t)(p+1)*M + mhi] = v11; }
            }
        }
    }
    if (statG) {
        float sg[NI], qg[NI];
        #pragma unroll
        for (int g2 = 0; g2 < NI; g2++) { sg[g2] = 0.f; qg[g2] = 0.f; }
        #pragma unroll
        for (int i = 0; i < NI; i++) {
            int grp = (warpM*NI + i) >> 1;
            int mlo = m0 + warpM*(NI*16) + i*16 + g;
            int mhi = mlo + 8;
            float blo = (bias && mlo < M) ? bias[mlo] : 0.f;
            float bhi = (bias && mhi < M) ? bias[mhi] : 0.f;
            #pragma unroll
            for (int j = 0; j < 4; j++) {
                float v00 = acc[i][j][0] + blo;
                float v01 = acc[i][j][1] + blo;
                float v10 = acc[i][j][2] + bhi;
                float v11 = acc[i][j][3] + bhi;
                if (mlo >= M) { v00 = 0.f; v01 = 0.f; }
                if (mhi >= M) { v10 = 0.f; v11 = 0.f; }
                sg[grp] += v00 + v01 + v10 + v11;
                qg[grp] += v00*v00 + v01*v01 + v10*v10 + v11*v11;
            }
        }
        const unsigned fm = 0xFFFFFFFFu;
        #pragma unroll
        for (int g2 = 0; g2 < NI; g2++) {
            sg[g2] += __shfl_xor_sync(fm, sg[g2], 1); sg[g2] += __shfl_xor_sync(fm, sg[g2], 2);
            qg[g2] += __shfl_xor_sync(fm, qg[g2], 1); qg[g2] += __shfl_xor_sync(fm, qg[g2], 2);
        }
        if (tg == 0) {
            #pragma unroll
            for (int g2 = 0; g2 < NI; g2++) {
                if (sg[g2] != 0.f || qg[g2] != 0.f) {
                    atomicAdd(&sS[g2], sg[g2]); atomicAdd(&sQ[g2], qg[g2]);
                }
            }
        }
        __syncthreads();
        if (t < NI && (m0/32 + t) < statG) {
            int bg = statOff + bb*statG + m0/32 + t;
            atomicAdd(&g_sum[0][bg], (double)sS[t]);
            atomicAdd(&g_sum[1][bg], (double)sQ[t]);
        }
    }
}

// ------------------------- group-norm statistics (fuse layer) ----------------
__global__ void stats_kernel(const float* __restrict__ in, long bStride, long gSize,
                             int G, int off)
{
    int bg = blockIdx.y;
    int b = bg / G, g = bg % G;
    const float* p = in + (size_t)b*bStride + (size_t)g*gSize;
    float s = 0.f, ss = 0.f;
    for (long i = (long)blockIdx.x*blockDim.x + threadIdx.x; i < gSize;
         i += (long)gridDim.x*blockDim.x) {
        float v = p[i];
        s += v; ss = fmaf(v, v, ss);
    }
    __shared__ double sh0[256], sh1[256];
    int t = threadIdx.x;
    sh0[t] = (double)s; sh1[t] = (double)ss;
    __syncthreads();
    for (int o = 128; o; o >>= 1) {
        if (t < o) { sh0[t] += sh0[t+o]; sh1[t] += sh1[t+o]; }
        __syncthreads();
    }
    if (t == 0) {
        atomicAdd(&g_sum[0][off + bg], sh0[0]);
        atomicAdd(&g_sum[1][off + bg], sh1[0]);
    }
}

__global__ void coeff_kernel(const float* __restrict__ gnw, const float* __restrict__ gnb,
                             int C, int Cg, double count, int off,
                             float* __restrict__ cA, float* __restrict__ cB)
{
    int i = blockIdx.x*blockDim.x + threadIdx.x;
    if (i >= BEFF*C) return;
    int b = i / C, ch = i % C;
    int G = C / Cg;
    int bg = off + b*G + ch/Cg;
    double mean = g_sum[0][bg] / count;
    double var  = g_sum[1][bg] / count - mean*mean;
    float rstd = (float)(1.0 / sqrt(var + 1e-5));
    float a = rstd * gnw[ch];
    cA[i] = a;
    cB[i] = gnb[ch] - (float)mean * a;
}

// ------------------------- feat from max/min ---------------------------------
__global__ void featmax_kernel(const float* __restrict__ mx, const float* __restrict__ mn,
                               const float* __restrict__ cA, const float* __restrict__ cB,
                               float* __restrict__ feat)
{
    int i = blockIdx.x*256 + threadIdx.x;
    if (i >= BEFF*192*NPTS) return;
    int b = i / (192*NPTS);
    int c = (i / NPTS) % 192;
    float a = cA[b*192+c];
    float base = (a > 0.f) ? mx[i] : mn[i];
    feat[i] = fmaxf(fmaf(a, base, cB[b*192+c]), 0.f);
}

// ------------------------- softmax with fused colsum atomics -----------------
__global__ void softmax_kernel(float* __restrict__ att, float* __restrict__ cs)
{
    size_t row = blockIdx.x;
    int b = (int)(row >> 11);
    float* p = att + row*NPTS;
    float* csb = cs + (size_t)b*NPTS;
    int t = threadIdx.x;
    float v[8];
    float mx = -1e30f;
    #pragma unroll
    for (int j = 0; j < 8; j++) { v[j] = p[t + j*256]; mx = fmaxf(mx, v[j]); }
    __shared__ float sh[256];
    sh[t] = mx; __syncthreads();
    for (int o = 128; o; o >>= 1) { if (t < o) sh[t] = fmaxf(sh[t], sh[t+o]); __syncthreads(); }
    mx = sh[0]; __syncthreads();
    float s = 0.f;
    #pragma unroll
    for (int j = 0; j < 8; j++) { v[j] = expf(v[j] - mx); s += v[j]; }
    sh[t] = s; __syncthreads();
    for (int o = 128; o; o >>= 1) { if (t < o) sh[t] += sh[t+o]; __syncthreads(); }
    float inv = 1.f / sh[0];
    #pragma unroll
    for (int j = 0; j < 8; j++) {
        float val = v[j]*inv;
        p[t + j*256] = val;
        atomicAdd(&csb[t + j*256], val);
    }
}

__global__ void update_kernel(const float* __restrict__ t_,
                              const float* __restrict__ cA, const float* __restrict__ cB,
                              float* __restrict__ feat, float* __restrict__ cat, int blk)
{
    size_t i = (size_t)blockIdx.x*256 + threadIdx.x;
    if (i >= (size_t)BEFF*192*NPTS) return;
    int b = (int)(i / (192*NPTS));
    int r = (int)(i % (192*NPTS));
    int c = r / NPTS, n = r % NPTS;
    float a = cA[b*192+c], bb = cB[b*192+c];
    float v = fmaxf(fmaf(a, t_[i], bb), 0.f);
    float x = feat[i] + v;
    feat[i] = x;
    cat[((size_t)b*768 + blk*192 + c)*NPTS + n] = x;
}

// ------------------------- final: gn + leaky + L2 normalize -----------------
__global__ void final_kernel(const float* __restrict__ fused,
                             const float* __restrict__ cA, const float* __restrict__ cB,
                             float* __restrict__ out)
{
    int b = blockIdx.y, n = blockIdx.x, t = threadIdx.x;
    float v[3]; float ss = 0.f;
    #pragma unroll
    for (int j = 0; j < 3; j++) {
        int c = t + j*256;
        float x = fused[((size_t)(b*768 + c))*NPTS + n];
        x = fmaf(cA[b*768+c], x, cB[b*768+c]);
        x = (x >= 0.f) ? x : 0.2f*x;
        v[j] = x; ss = fmaf(x, x, ss);
    }
    __shared__ float sh[256];
    sh[t] = ss; __syncthreads();
    for (int o = 128; o; o >>= 1) { if (t < o) sh[t] += sh[t+o]; __syncthreads(); }
    float inv = 1.f / (sqrtf(sh[0]) + 1e-8f);
    #pragma unroll
    for (int j = 0; j < 3; j++) {
        int c = t + j*256;
        out[((size_t)b*NPTS + n)*768 + c] = v[j]*inv;
    }
}

// ------------------------- host side ----------------------------------------
template<int NI>
static void launch_gemm(const float* W, long sW, const float* B, long sB,
                        const float* B2, const float* bias, const float* cs,
                        float* Out, long sOut, float* OutT,
                        int M, int Kd, int P, int statG, int statOff)
{
    dim3 grid(P/128, (M + NI*32 - 1)/(NI*32), BEFF);
    gemm_tc_kernel<NI><<<grid, 256>>>(W, sW, B, sB, B2, bias, cs,
                                      Out, sOut, OutT, M, Kd, P, statG, statOff);
}

extern "C" void kernel_launch(void* const* d_in, const int* in_sizes, int n_in,
                              void* d_out, int out_size)
{
    const float* src     = (const float*)d_in[0];
    const float* tgt     = (const float*)d_in[1];
    const float* lf_w0   = (const float*)d_in[5];
    const float* lf_gnw0 = (const float*)d_in[6];
    const float* lf_gnb0 = (const float*)d_in[7];
    const float* lf_w1   = (const float*)d_in[8];
    const float* lf_gnw1 = (const float*)d_in[9];
    const float* lf_gnb1 = (const float*)d_in[10];
    const float* lf_w2   = (const float*)d_in[11];
    const float* lf_gnw2 = (const float*)d_in[12];
    const float* lf_gnb2 = (const float*)d_in[13];
    const float* qk_w    = (const float*)d_in[14];
    const float* v_w     = (const float*)d_in[15];
    const float* v_b     = (const float*)d_in[16];
    const float* t_w     = (const float*)d_in[17];
    const float* t_b     = (const float*)d_in[18];
    const float* blk_gnw = (const float*)d_in[19];
    const float* blk_gnb = (const float*)d_in[20];
    const float* fuse_w  = (const float*)d_in[21];
    const float* fuse_gnw= (const float*)d_in[22];
    const float* fuse_gnb= (const float*)d_in[23];

    int*    pidx;   cudaGetSymbolAddress((void**)&pidx,   g_idx);
    __half* pact2;  cudaGetSymbolAddress((void**)&pact2,  g_act2h);
    float*  pmx;    cudaGetSymbolAddress((void**)&pmx,    g_mx);
    float*  pmn;    cudaGetSymbolAddress((void**)&pmn,    g_mn);
    float*  pW1f;   cudaGetSymbolAddress((void**)&pW1f,   g_W1f);
    float*  pqkw;   cudaGetSymbolAddress((void**)&pqkw,   g_qkw64);
    float*  pfeat;  cudaGetSymbolAddress((void**)&pfeat,  g_feat);
    float*  pq;     cudaGetSymbolAddress((void**)&pq,     g_q);
    float*  pqT;    cudaGetSymbolAddress((void**)&pqT,    g_qT);
    float*  pv;     cudaGetSymbolAddress((void**)&pv,     g_v);
    float*  patt;   cudaGetSymbolAddress((void**)&patt,   g_att);
    float*  pcs4;   cudaGetSymbolAddress((void**)&pcs4,   g_cs4);
    float*  pxr;    cudaGetSymbolAddress((void**)&pxr,    g_xr);
    float*  pt;     cudaGetSymbolAddress((void**)&pt,     g_t);
    float*  pcat;   cudaGetSymbolAddress((void**)&pcat,   g_cat);
    float*  pfused; cudaGetSymbolAddress((void**)&pfused, g_fused);
    float*  pcA;    cudaGetSymbolAddress((void**)&pcA,    g_coefA);
    float*  pcB;    cudaGetSymbolAddress((void**)&pcB,    g_coefB);

    // 1) ball query + zero stats/colsum arenas
    ballq_kernel<<<dim3(NPTS/256, BEFF), 256>>>(src, tgt, pidx);
    zero_all_kernel<<<1, 256>>>();

    // 2) analytic GN1 -> folded W1f
    gram_kernel<<<dim3(64, BEFF), 256>>>(src, tgt, pidx);
    coeff1_kernel<<<BEFF, 128>>>(lf_w0, lf_gnw0, lf_gnb0, pW1f);

    // 3) layer2 fused GEMM (fp16 MMA) -> fp16 act2, GN2 stats fused
    layer2_kernel<<<dim3(PBIG/128, 2, BEFF), 256>>>(lf_w1, src, tgt, pidx, pW1f, pact2);
    coeff_kernel<<<(BEFF*256 + 255)/256, 256>>>(lf_gnw1, lf_gnb1, 256, 32,
                                                (double)(32L*PBIG), OFF_GN2, pcA, pcB);

    // 4) layer3 fused GEMM (fp16 MMA, 96-row tiles), max/min + GN3 stats
    layer3_kernel<<<dim3(PBIG/128, 2, BEFF), 256>>>(lf_w2, pact2, pcA, pcB, pmx, pmn);
    coeff_kernel<<<(BEFF*192 + 255)/256, 256>>>(lf_gnw2, lf_gnb2, 192, 32,
                                                (double)(32L*PBIG), OFF_GN3, pcA, pcB);

    // 5) feat = relu(gn3(max over K))
    featmax_kernel<<<(BEFF*192*NPTS + 255)/256, 256>>>(pmx, pmn, pcA, pcB, pfeat);

    // 6) four attention blocks
    for (int i = 0; i < 4; i++) {
        // pad qk_w -> 64x192 (rows 48-63 zero)
        pad_qkw_kernel<<<(64*192 + 255)/256, 256>>>(qk_w + (size_t)i*48*192);
        // q = qkw64 . feat  (M=64 incl. zero rows), fused qT epilogue (stride 64)
        launch_gemm<2>(pqkw, 0L, pfeat, 192L*NPTS,
                       nullptr, nullptr, nullptr, pq, 64L*NPTS, pqT,
                       64, 192, NPTS, 0, 0);
        // v = v_w . feat + v_b (M=192)
        launch_gemm<3>(v_w + (size_t)i*192*192, 0L, pfeat, 192L*NPTS,
                       nullptr, v_b + i*192, nullptr, pv, 192L*NPTS, nullptr,
                       192, 192, NPTS, 0, 0);
        // att = qT . q  (fp16, Kd=64 padded)
        launch_gemm<4>(pqT, (long)NPTS*64, pq, 64L*NPTS,
                       nullptr, nullptr, nullptr, patt, (long)NPTS*NPTS, nullptr,
                       NPTS, 64, NPTS, 0, 0);
        // softmax + fused column-sum atomics into g_cs4[i]
        softmax_kernel<<<BEFF*NPTS, 256>>>(patt, pcs4 + (size_t)i*BEFF*NPTS);
        // x_r = v . (att * 1/(1e-9+colsum))  — normalize-then-round
        launch_gemm<3>(pv, 192L*NPTS, patt, (long)NPTS*NPTS,
                       nullptr, nullptr, pcs4 + (size_t)i*BEFF*NPTS,
                       pxr, 192L*NPTS, nullptr, 192, NPTS, NPTS, 0, 0);
        // t = t_w . (feat - x_r) + t_b, GN stats fused
        launch_gemm<3>(t_w + (size_t)i*192*192, 0L, pfeat, 192L*NPTS,
                       pxr, t_b + i*192, nullptr, pt, 192L*NPTS, nullptr,
                       192, 192, NPTS, 6, OFF_BLK + i*64);
        coeff_kernel<<<(BEFF*192 + 255)/256, 256>>>(blk_gnw + i*192, blk_gnb + i*192,
                                                    192, 32, (double)(32L*NPTS),
                                                    OFF_BLK + i*64, pcA, pcB);
        update_kernel<<<(BEFF*192*NPTS + 255)/256, 256>>>(pt, pcA, pcB, pfeat, pcat, i);
    }

    // 7) fuse 768->768 (fp16 MMA)
    launch_gemm<4>(fuse_w, 0L, pcat, 768L*NPTS,
                   nullptr, nullptr, nullptr, pfused, 768L*NPTS, nullptr,
                   768, 768, NPTS, 0, 0);
    stats_kernel<<<dim3(64, BEFF*16), 256>>>(pfused, 768L*NPTS, 48L*NPTS, 16, OFF_FUSE);
    coeff_kernel<<<(BEFF*768 + 255)/256, 256>>>(fuse_gnw, fuse_gnb, 768, 48,
                                                (double)(48L*NPTS), OFF_FUSE, pcA, pcB);

    // 8) gn + leaky_relu + transpose + L2 normalize -> d_out
    final_kernel<<<dim3(NPTS, BEFF), 256>>>(pfused, pcA, pcB, (float*)d_out);
}

// round 16
// speedup vs baseline: 1.0091x; 1.0091x over previous
#include <cuda_runtime.h>
#include <cuda_fp16.h>
#include <math.h>
#include <float.h>
#include <stdint.h>

#define NPTS 2048
#define KNN 64
#define BEFF 4
#define PBIG (KNN*NPTS)   // 131072
#define R2 0.09f

// ------------------------- scratch (device globals; no allocs allowed) -------
__device__ int    g_idx[BEFF*NPTS*KNN];
__device__ __half g_act2h[(size_t)BEFF*256*PBIG];
__device__ float  g_mx[BEFF*192*NPTS];
__device__ float  g_mn[BEFF*192*NPTS];
__device__ float  g_feat[BEFF*192*NPTS];
__device__ float  g_q  [BEFF*64*NPTS];          // padded head dim 48->64
__device__ float  g_qT [BEFF*NPTS*64];
__device__ float  g_v  [BEFF*192*NPTS];
__device__ float  g_att[(size_t)BEFF*NPTS*NPTS];
__device__ float  g_cs [BEFF*NPTS];
__device__ float  g_xr [BEFF*192*NPTS];
__device__ float  g_t  [BEFF*192*NPTS];
__device__ float  g_cat[BEFF*768*NPTS];
__device__ float  g_fused[BEFF*768*NPTS];
__device__ double g_sum[2][512];
__device__ double g_gram[BEFF][28];
__device__ float  g_W1f[BEFF*128*8];
__device__ float  g_qkw64[4*64*192];
__device__ float  g_coefA[BEFF*768];
__device__ float  g_coefB[BEFF*768];

#define OFF_GN2   0
#define OFF_GN3   64
#define OFF_BLK   128
#define OFF_FUSE  384

__device__ __forceinline__ uint32_t packh2(float a, float b) {
    __half2 h = __floats2half2_rn(a, b);
    return *(uint32_t*)&h;
}
__device__ __forceinline__ float4 ld4(const float* p) { return *(const float4*)p; }
__device__ __forceinline__ float4 ld4(const __half* p) {
    uint2 u = *(const uint2*)p;
    __half2 h0 = *(__half2*)&u.x, h1 = *(__half2*)&u.y;
    float2 a = __half22float2(h0), b = __half22float2(h1);
    return make_float4(a.x, a.y, b.x, b.y);
}
__device__ __forceinline__ void st2(__half* p, float a, float b) {
    *(__half2*)p = __floats2half2_rn(a, b);
}

#define MMA_F16(d, a, b0v) \
    asm volatile( \
        "mma.sync.aligned.m16n8k16.row.col.f32.f16.f16.f32 " \
        "{%0,%1,%2,%3}, {%4,%5,%6,%7}, {%8,%9}, {%0,%1,%2,%3};\n" \
        : "+f"(d[0]), "+f"(d[1]), "+f"(d[2]), "+f"(d[3]) \
        : "r"(a.x), "r"(a.y), "r"(a.z), "r"(a.w), "r"(b0v[0]), "r"(b0v[1]))

// ------------------------- ball query ---------------------------------------
__global__ void ballq_kernel(const float* __restrict__ src,
                             const float* __restrict__ tgt,
                             int* __restrict__ idxout)
{
    int b = blockIdx.y;
    const float* xyz = (b < 2) ? src + (size_t)b*NPTS*3 : tgt + (size_t)(b-2)*NPTS*3;
    __shared__ float sx[NPTS], sy[NPTS], sz[NPTS], sq[NPTS];
    for (int i = threadIdx.x; i < NPTS; i += blockDim.x) {
        float x = xyz[i*3], y = xyz[i*3+1], z = xyz[i*3+2];
        sx[i] = x; sy[i] = y; sz[i] = z;
        sq[i] = x*x + y*y + z*z;
    }
    __syncthreads();
    int m = blockIdx.x*blockDim.x + threadIdx.x;
    float qx = sx[m], qy = sy[m], qz = sz[m], qs = sq[m];
    int* o = idxout + ((size_t)b*NPTS + m)*KNN;
    int cnt = 0;
    for (int j = 0; j < NPTS && cnt < KNN; j++) {
        float d = qs + sq[j] - 2.f*(qx*sx[j] + qy*sy[j] + qz*sz[j]);
        if (d <= R2) o[cnt++] = j;
    }
    int f0 = o[0];
    for (; cnt < KNN; cnt++) o[cnt] = f0;
}

// ------------------------- zero (gram + stats arena) -------------------------
__global__ void zero_all_kernel() {
    int t = threadIdx.x;
    for (int i = t; i < 1024; i += 256) ((double*)g_sum)[i] = 0.0;
    if (t < BEFF*28) ((double*)g_gram)[t] = 0.0;
}

// ------------------------- feature gram (analytic GN1 stats) -----------------
__global__ void gram_kernel(const float* __restrict__ src,
                            const float* __restrict__ tgt,
                            const int* __restrict__ idx)
{
    int b = blockIdx.y;
    const float* xyz = (b < 2) ? src + (size_t)b*NPTS*3 : tgt + (size_t)(b-2)*NPTS*3;
    float acc[27];
    #pragma unroll
    for (int i = 0; i < 27; i++) acc[i] = 0.f;
    for (int pos = blockIdx.x*256 + threadIdx.x; pos < PBIG; pos += 64*256) {
        int n = pos >> 6, k = pos & 63;
        int j = idx[((size_t)b*NPTS + n)*KNN + k];
        float f[6];
        f[0] = xyz[n*3]; f[1] = xyz[n*3+1]; f[2] = xyz[n*3+2];
        f[3] = xyz[j*3]   - f[0];
        f[4] = xyz[j*3+1] - f[1];
        f[5] = xyz[j*3+2] - f[2];
        #pragma unroll
        for (int i = 0; i < 6; i++) acc[i] += f[i];
        int c = 6;
        #pragma unroll
        for (int i = 0; i < 6; i++)
            #pragma unroll
            for (int jj = i; jj < 6; jj++)
                acc[c++] += f[i]*f[jj];
    }
    #pragma unroll
    for (int i = 0; i < 27; i++)
        #pragma unroll
        for (int o = 16; o; o >>= 1)
            acc[i] += __shfl_down_sync(0xFFFFFFFFu, acc[i], o);
    __shared__ float sh[8][27];
    int lane = threadIdx.x & 31, w = threadIdx.x >> 5;
    if (lane == 0)
        #pragma unroll
        for (int i = 0; i < 27; i++) sh[w][i] = acc[i];
    __syncthreads();
    if (threadIdx.x < 27) {
        double s = 0.0;
        for (int ww = 0; ww < 8; ww++) s += (double)sh[ww][threadIdx.x];
        atomicAdd(&g_gram[b][threadIdx.x], s);
    }
}

// ------------------------- coeff1: analytic GN1 -> folded W1f ---------------
__global__ void coeff1_kernel(const float* __restrict__ W1,
                              const float* __restrict__ gnw,
                              const float* __restrict__ gnb,
                              float* __restrict__ W1f)
{
    int b = blockIdx.x, c = threadIdx.x;
    double S[6], G[21];
    #pragma unroll
    for (int i = 0; i < 6; i++) S[i] = g_gram[b][i];
    #pragma unroll
    for (int i = 0; i < 21; i++) G[i] = g_gram[b][6+i];
    float w[6];
    #pragma unroll
    for (int i = 0; i < 6; i++) w[i] = W1[c*6+i];
    double s = 0.0, q = 0.0;
    #pragma unroll
    for (int i = 0; i < 6; i++) s += (double)w[i]*S[i];
    {
        int ci = 0;
        #pragma unroll
        for (int i = 0; i < 6; i++)
            #pragma unroll
            for (int j = i; j < 6; j++, ci++)
                q += (i==j ? 1.0 : 2.0) * (double)w[i]*(double)w[j]*G[ci];
    }
    double ss = s, qq = q;
    #pragma unroll
    for (int o = 16; o; o >>= 1) {
        ss += __shfl_down_sync(0xFFFFFFFFu, ss, o);
        qq += __shfl_down_sync(0xFFFFFFFFu, qq, o);
    }
    ss = __shfl_sync(0xFFFFFFFFu, ss, 0);
    qq = __shfl_sync(0xFFFFFFFFu, qq, 0);
    double count = 32.0 * (double)PBIG;
    double mean = ss / count;
    double var  = qq / count - mean*mean;
    float a  = gnw[c] * (float)(1.0 / sqrt(var + 1e-5));
    float b2 = gnb[c] - (float)mean * a;
    float* dst = W1f + ((size_t)b*128 + c)*8;
    #pragma unroll
    for (int i = 0; i < 6; i++) dst[i] = a*w[i];
    dst[6] = b2; dst[7] = 0.f;
}

// ------------------------- pad qk_w (all 4 blocks) 48x192 -> 64x192 ----------
__global__ void pad_qkw_kernel(const float* __restrict__ qkw)
{
    int i = blockIdx.x*256 + threadIdx.x;
    if (i >= 4*64*192) return;
    int blk = i / (64*192);
    int r = i % (64*192);
    int row = r / 192;
    g_qkw64[i] = (row < 48) ? qkw[(size_t)blk*48*192 + r] : 0.f;
}

// ------------------------- layer2 fused GEMM (fp16 MMA, BK=32) ---------------
__global__ void __launch_bounds__(256) layer2_kernel(
    const float* __restrict__ W,
    const float* __restrict__ src, const float* __restrict__ tgt,
    const int* __restrict__ idx,
    const float* __restrict__ W1f,
    __half* __restrict__ out)
{
    const int bb = blockIdx.z;
    const int m0 = blockIdx.y * 128;
    const int p0 = blockIdx.x * 128;
    const float* xyz = (bb < 2) ? src + (size_t)bb*NPTS*3 : tgt + (size_t)(bb-2)*NPTS*3;
    __half* Ob = out + (size_t)bb*256*PBIG;

    __shared__ uint32_t sA[2][2048];
    __shared__ uint32_t sB_[2][2176];
    __shared__ float sF[7*132];
    __shared__ float sW1[128*8];
    __shared__ float sS[4], sQ[4];

    const int t = threadIdx.x;
    const int lane = t & 31;
    const int w = t >> 5;
    const int warpM = w >> 2;
    const int warpN = w & 3;
    const int g  = lane >> 2;
    const int tg = lane & 3;

    for (int i = t; i < 128*8; i += 256) sW1[i] = W1f[(size_t)bb*128*8 + i];
    if (t < 128) {
        int col = t;
        int n = (p0 >> 6) + (col >> 6);
        int k = col & 63;
        int j = idx[((size_t)bb*NPTS + n)*KNN + k];
        float cx = xyz[n*3], cy = xyz[n*3+1], cz = xyz[n*3+2];
        sF[0*132+col] = cx; sF[1*132+col] = cy; sF[2*132+col] = cz;
        sF[3*132+col] = xyz[j*3]   - cx;
        sF[4*132+col] = xyz[j*3+1] - cy;
        sF[5*132+col] = xyz[j*3+2] - cz;
        sF[6*132+col] = 1.f;
    }
    if (t < 4) { sS[t] = 0.f; sQ[t] = 0.f; }

    float acc[4][4][4];
    #pragma unroll
    for (int i = 0; i < 4; i++)
        #pragma unroll
        for (int j = 0; j < 4; j++)
            #pragma unroll
            for (int r = 0; r < 4; r++) acc[i][j][r] = 0.f;

    float4 rA[2][2];
    auto loadA = [&](int k0) {
        #pragma unroll
        for (int i = 0; i < 2; i++) {
            int f = t*2 + i;
            int m = f >> 2, kq = f & 3;
            const float* sp = W + (size_t)(m0+m)*128 + k0 + kq*8;
            rA[i][0] = *(const float4*)sp;
            rA[i][1] = *(const float4*)(sp+4);
        }
    };
    auto storeA = [&](int buf) {
        #pragma unroll
        for (int i = 0; i < 2; i++) {
            int f = t*2 + i;
            int m = f >> 2, kq = f & 3;
            float vv[8] = {rA[i][0].x, rA[i][0].y, rA[i][0].z, rA[i][0].w,
                           rA[i][1].x, rA[i][1].y, rA[i][1].z, rA[i][1].w};
            int mf = m >> 4, mm = m & 15;
            int gg = mm & 7, hi = mm >> 3;
            #pragma unroll
            for (int e2 = 0; e2 < 4; e2++) {
                int k = kq*8 + e2*2;
                int kc = k >> 4, kk = k & 15;
                int khi = kk >> 3, tg2 = (kk >> 1) & 3;
                int r = hi + 2*khi;
                sA[buf][((kc*8 + mf)*32 + gg*4 + tg2)*4 + r] = packh2(vv[e2*2], vv[e2*2+1]);
            }
        }
    };
    auto computeB = [&](int k0, int buf) {
        #pragma unroll
        for (int i = 0; i < 2; i++) {
            int f = t + i*256;
            int k2 = f >> 5, pq = f & 31;
            const float* wa = &sW1[(k0 + 2*k2    )*8];
            const float* wb = &sW1[(k0 + 2*k2 + 1)*8];
            uint32_t* dst = &sB_[buf][k2*136 + pq*4];
            #pragma unroll
            for (int e = 0; e < 4; e++) {
                int c4 = pq*4 + e;
                float va = wa[6], vb = wb[6];
                #pragma unroll
                for (int ii = 0; ii < 6; ii++) {
                    float fv = sF[ii*132 + c4];
                    va = fmaf(wa[ii], fv, va);
                    vb = fmaf(wb[ii], fv, vb);
                }
                va = fmaxf(va, 0.f); vb = fmaxf(vb, 0.f);
                dst[e] = packh2(va, vb);
            }
        }
    };
    __syncthreads();

    loadA(0); storeA(0); computeB(0, 0);
    __syncthreads();
    int cur = 0;
    for (int k0 = 0; k0 < 128; k0 += 32) {
        int nk = k0 + 32;
        bool more = nk < 128;
        if (more) loadA(nk);
        #pragma unroll
        for (int kc = 0; kc < 2; kc++) {
            uint4 af[4];
            #pragma unroll
            for (int i = 0; i < 4; i++)
                af[i] = ((const uint4*)sA[cur])[(kc*8 + warpM*4 + i)*32 + lane];
            uint32_t b0[4][2];
            #pragma unroll
            for (int j = 0; j < 4; j++) {
                int col = warpN*32 + j*8 + g;
                b0[j][0] = sB_[cur][(kc*8 + tg  )*136 + col];
                b0[j][1] = sB_[cur][(kc*8 + tg+4)*136 + col];
            }
            #pragma unroll
            for (int i = 0; i < 4; i++)
                #pragma unroll
                for (int j = 0; j < 4; j++)
                    MMA_F16(acc[i][j], af[i], b0[j]);
        }
        if (more) { storeA(cur^1); computeB(nk, cur^1); }
        __syncthreads();
        cur ^= 1;
    }

    float s0 = 0.f, q0 = 0.f, s1 = 0.f, q1 = 0.f;
    #pragma unroll
    for (int i = 0; i < 4; i++) {
        int mlo = m0 + warpM*64 + i*16 + g;
        int mhi = mlo + 8;
        #pragma unroll
        for (int j = 0; j < 4; j++) {
            int p = p0 + warpN*32 + j*8 + 2*tg;
            st2(&Ob[(size_t)mlo*PBIG + p], acc[i][j][0], acc[i][j][1]);
            st2(&Ob[(size_t)mhi*PBIG + p], acc[i][j][2], acc[i][j][3]);
            #pragma unroll
            for (int r = 0; r < 4; r++) {
                float v = acc[i][j][r];
                if (i < 2) { s0 += v; q0 = fmaf(v, v, q0); }
                else       { s1 += v; q1 = fmaf(v, v, q1); }
            }
        }
    }
    const unsigned fm = 0xFFFFFFFFu;
    s0 += __shfl_xor_sync(fm, s0, 1); s0 += __shfl_xor_sync(fm, s0, 2);
    q0 += __shfl_xor_sync(fm, q0, 1); q0 += __shfl_xor_sync(fm, q0, 2);
    s1 += __shfl_xor_sync(fm, s1, 1); s1 += __shfl_xor_sync(fm, s1, 2);
    q1 += __shfl_xor_sync(fm, q1, 1); q1 += __shfl_xor_sync(fm, q1, 2);
    if (tg == 0) {
        atomicAdd(&sS[warpM*2+0], s0); atomicAdd(&sQ[warpM*2+0], q0);
        atomicAdd(&sS[warpM*2+1], s1); atomicAdd(&sQ[warpM*2+1], q1);
    }
    __syncthreads();
    if (t < 4) {
        int bg = OFF_GN2 + bb*8 + m0/32 + t;
        atomicAdd(&g_sum[0][bg], (double)sS[t]);
        atomicAdd(&g_sum[1][bg], (double)sQ[t]);
    }
}

// ------------------------- layer3 fused GEMM (fp16 MMA, 96-row tiles) --------
__global__ void __launch_bounds__(256) layer3_kernel(
    const float* __restrict__ W,
    const __half* __restrict__ act2,
    const float* __restrict__ cA2, const float* __restrict__ cB2,
    float* __restrict__ mxbuf, float* __restrict__ mnbuf)
{
    const int bb = blockIdx.z;
    const int m0 = blockIdx.y * 96;
    const int p0 = blockIdx.x * 128;
    const __half* Bb = act2 + (size_t)bb*256*PBIG;
    const float* cAb = cA2 + bb*256;
    const float* cBb = cB2 + bb*256;

    __shared__ uint32_t sA[2][1536];
    __shared__ uint32_t sB_[2][2176];
    __shared__ float sMx[2][96], sMn[2][96];
    __shared__ float sS[4], sQ[4];

    const int t = threadIdx.x;
    const int lane = t & 31;
    const int w = t >> 5;
    const int warpM = w >> 2;
    const int warpN = w & 3;
    const int g  = lane >> 2;
    const int tg = lane & 3;
    const int nh = warpN >> 1;

    if (t < 4) { sS[t] = 0.f; sQ[t] = 0.f; }

    float acc[3][4][4];
    #pragma unroll
    for (int i = 0; i < 3; i++)
        #pragma unroll
        for (int j = 0; j < 4; j++)
            #pragma unroll
            for (int r = 0; r < 4; r++) acc[i][j][r] = 0.f;

    float4 rA[2][2], rB0[2], rB1[2];
    auto loadAB = [&](int k0) {
        #pragma unroll
        for (int i = 0; i < 2; i++) {
            int f = t*2 + i;
            if (f < 384) {
                int m = f >> 2, kq = f & 3;
                const float* sp = W + (size_t)(m0+m)*256 + k0 + kq*8;
                rA[i][0] = *(const float4*)sp;
                rA[i][1] = *(const float4*)(sp+4);
            }
        }
        #pragma unroll
        for (int i = 0; i < 2; i++) {
            int f = t + i*256;
            int k2 = f >> 5, pq = f & 31;
            rB0[i] = ld4(Bb + (size_t)(k0 + 2*k2    )*PBIG + p0 + pq*4);
            rB1[i] = ld4(Bb + (size_t)(k0 + 2*k2 + 1)*PBIG + p0 + pq*4);
        }
    };
    auto storeAB = [&](int k0, int buf) {
        #pragma unroll
        for (int i = 0; i < 2; i++) {
            int f = t*2 + i;
            if (f < 384) {
                int m = f >> 2, kq = f & 3;
                float vv[8] = {rA[i][0].x, rA[i][0].y, rA[i][0].z, rA[i][0].w,
                               rA[i][1].x, rA[i][1].y, rA[i][1].z, rA[i][1].w};
                int mf = m >> 4, mm = m & 15;
                int gg = mm & 7, hi = mm >> 3;
                #pragma unroll
                for (int e2 = 0; e2 < 4; e2++) {
                    int k = kq*8 + e2*2;
                    int kc = k >> 4, kk = k & 15;
                    int khi = kk >> 3, tg2 = (kk >> 1) & 3;
                    int r = hi + 2*khi;
                    sA[buf][((kc*6 + mf)*32 + gg*4 + tg2)*4 + r] = packh2(vv[e2*2], vv[e2*2+1]);
                }
            }
        }
        #pragma unroll
        for (int i = 0; i < 2; i++) {
            int f = t + i*256;
            int k2 = f >> 5, pq = f & 31;
            int ka = k0 + 2*k2, kb = ka + 1;
            float aa = cAb[ka], ca = cBb[ka];
            float ab = cAb[kb], cb = cBb[kb];
            float va[4] = {rB0[i].x, rB0[i].y, rB0[i].z, rB0[i].w};
            float vb[4] = {rB1[i].x, rB1[i].y, rB1[i].z, rB1[i].w};
            uint32_t* dst = &sB_[buf][k2*136 + pq*4];
            #pragma unroll
            for (int e = 0; e < 4; e++) {
                float x = fmaxf(fmaf(aa, va[e], ca), 0.f);
                float y = fmaxf(fmaf(ab, vb[e], cb), 0.f);
                dst[e] = packh2(x, y);
            }
        }
    };

    loadAB(0); storeAB(0, 0);
    __syncthreads();
    int cur = 0;
    for (int k0 = 0; k0 < 256; k0 += 32) {
        int nk = k0 + 32;
        bool more = nk < 256;
        if (more) loadAB(nk);
        #pragma unroll
        for (int kc = 0; kc < 2; kc++) {
            uint4 af[3];
            #pragma unroll
            for (int i = 0; i < 3; i++)
                af[i] = ((const uint4*)sA[cur])[(kc*6 + warpM*3 + i)*32 + lane];
            uint32_t b0[4][2];
            #pragma unroll
            for (int j = 0; j < 4; j++) {
                int col = warpN*32 + j*8 + g;
                b0[j][0] = sB_[cur][(kc*8 + tg  )*136 + col];
                b0[j][1] = sB_[cur][(kc*8 + tg+4)*136 + col];
            }
            #pragma unroll
            for (int i = 0; i < 3; i++)
                #pragma unroll
                for (int j = 0; j < 4; j++)
                    MMA_F16(acc[i][j], af[i], b0[j]);
        }
        if (more) storeAB(nk, cur^1);
        __syncthreads();
        cur ^= 1;
    }

    const unsigned fm = 0xFFFFFFFFu;
    float sg[3] = {0.f,0.f,0.f}, qg[3] = {0.f,0.f,0.f};
    float rmx[6], rmn[6];
    #pragma unroll
    for (int i = 0; i < 3; i++) {
        int grp = (warpM*3 + i) >> 1;
        #pragma unroll
        for (int lh = 0; lh < 2; lh++) {
            float vmx = -FLT_MAX, vmn = FLT_MAX;
            #pragma unroll
            for (int j = 0; j < 4; j++) {
                float a = acc[i][j][lh*2], b2 = acc[i][j][lh*2+1];
                vmx = fmaxf(vmx, fmaxf(a, b2));
                vmn = fminf(vmn, fminf(a, b2));
                sg[grp] += a + b2;
                qg[grp] += a*a + b2*b2;
            }
            vmx = fmaxf(vmx, __shfl_xor_sync(fm, vmx, 1));
            vmx = fmaxf(vmx, __shfl_xor_sync(fm, vmx, 2));
            vmn = fminf(vmn, __shfl_xor_sync(fm, vmn, 1));
            vmn = fminf(vmn, __shfl_xor_sync(fm, vmn, 2));
            rmx[i*2+lh] = vmx; rmn[i*2+lh] = vmn;
        }
    }
    #pragma unroll
    for (int g2 = 0; g2 < 3; g2++) {
        sg[g2] += __shfl_xor_sync(fm, sg[g2], 1); sg[g2] += __shfl_xor_sync(fm, sg[g2], 2);
        qg[g2] += __shfl_xor_sync(fm, qg[g2], 1); qg[g2] += __shfl_xor_sync(fm, qg[g2], 2);
    }
    if (tg == 0) {
        #pragma unroll
        for (int g2 = 0; g2 < 3; g2++) {
            if (sg[g2] != 0.f || qg[g2] != 0.f) {
                atomicAdd(&sS[g2], sg[g2]); atomicAdd(&sQ[g2], qg[g2]);
            }
        }
        if ((warpN & 1) == 0) {
            #pragma unroll
            for (int i = 0; i < 3; i++)
                #pragma unroll
                for (int lh = 0; lh < 2; lh++) {
                    int mloc = warpM*48 + i*16 + g + lh*8;
                    sMx[nh][mloc] = rmx[i*2+lh];
                    sMn[nh][mloc] = rmn[i*2+lh];
                }
        }
    }
    __syncthreads();
    if (tg == 0 && (warpN & 1) == 1) {
        int n = (p0 >> 6) + nh;
        #pragma unroll
        for (int i = 0; i < 3; i++)
            #pragma unroll
            for (int lh = 0; lh < 2; lh++) {
                int mloc = warpM*48 + i*16 + g + lh*8;
                int m = m0 + mloc;
                float fx = fmaxf(rmx[i*2+lh], sMx[nh][mloc]);
                float fn = fminf(rmn[i*2+lh], sMn[nh][mloc]);
                size_t o = ((size_t)bb*192 + m)*NPTS + n;
                mxbuf[o] = fx; mnbuf[o] = fn;
            }
    }
    if (t < 3) {
        int bg = OFF_GN3 + bb*6 + m0/32 + t;
        atomicAdd(&g_sum[0][bg], (double)sS[t]);
        atomicAdd(&g_sum[1][bg], (double)sQ[t]);
    }
}

// ------------------------- generic fp16 GEMM (BK=32, Kd%32==0) ---------------
template<int NI>
__global__ void __launch_bounds__(256) gemm_tc_kernel(
    const float* __restrict__ W, long sW,
    const float* __restrict__ B, long sB,
    const float* __restrict__ B2,
    const float* __restrict__ bias,
    const float* __restrict__ colscale,
    float* __restrict__ Out, long sOut,
    float* __restrict__ OutT,
    int M, int Kd, int P, int statG, int statOff)
{
    const int bb = blockIdx.z;
    const int m0 = blockIdx.y * (NI*32);
    const int p0 = blockIdx.x * 128;
    const float* Wb  = W + (size_t)bb*sW;
    const float* Bb  = B + (size_t)bb*sB;
    const float* B2b = B2 ? B2 + (size_t)bb*sB : nullptr;
    float* Ob = Out + (size_t)bb*sOut;

    __shared__ uint32_t sA[2][512*NI];
    __shared__ uint32_t sB_[2][2176];
    __shared__ float sS[4], sQ[4];

    const int t = threadIdx.x;
    const int lane = t & 31;
    const int w = t >> 5;
    const int warpM = w >> 2;
    const int warpN = w & 3;
    const int g  = lane >> 2;
    const int tg = lane & 3;

    if (t < 4) { sS[t] = 0.f; sQ[t] = 0.f; }

    float acc[NI][4][4];
    #pragma unroll
    for (int i = 0; i < NI; i++)
        #pragma unroll
        for (int j = 0; j < 4; j++)
            #pragma unroll
            for (int r = 0; r < 4; r++) acc[i][j][r] = 0.f;

    float4 csv[2];
    #pragma unroll
    for (int i = 0; i < 2; i++) {
        if (colscale) {
            int pq = (t + i*256) & 31;
            float4 c = *(const float4*)(colscale + (size_t)bb*P + p0 + pq*4);
            csv[i] = make_float4(1.f/(1e-9f + c.x), 1.f/(1e-9f + c.y),
                                 1.f/(1e-9f + c.z), 1.f/(1e-9f + c.w));
        } else csv[i] = make_float4(1.f,1.f,1.f,1.f);
    }

    float4 rA[2][2], rB0[2], rB1[2], rC0[2], rC1[2];
    auto loadAB = [&](int k0) {
        #pragma unroll
        for (int i = 0; i < 2; i++) {
            int f = t*2 + i;
            if (f < 128*NI) {
                int m = f >> 2, kq = f & 3;
                int gm = m0 + m;
                if (gm < M) {
                    const float* sp = Wb + (size_t)gm*Kd + k0 + kq*8;
                    rA[i][0] = *(const float4*)sp;
                    rA[i][1] = *(const float4*)(sp+4);
                } else {
                    rA[i][0] = make_float4(0.f,0.f,0.f,0.f);
                    rA[i][1] = make_float4(0.f,0.f,0.f,0.f);
                }
            }
        }
        #pragma unroll
        for (int i = 0; i < 2; i++) {
            int f = t + i*256;
            int pq = f & 31;
            int k2 = f >> 5;
            size_t off0 = (size_t)(k0 + 2*k2)*P + p0 + pq*4;
            rB0[i] = *(const float4*)(Bb + off0);
            rB1[i] = *(const float4*)(Bb + off0 + P);
            if (B2b) {
                rC0[i] = *(const float4*)(B2b + off0);
                rC1[i] = *(const float4*)(B2b + off0 + P);
            }
        }
    };
    auto storeAB = [&](int k0, int buf) {
        #pragma unroll
        for (int i = 0; i < 2; i++) {
            int f = t*2 + i;
            if (f < 128*NI) {
                int m = f >> 2, kq = f & 3;
                int mf = m >> 4, mm = m & 15;
                int gg = mm & 7, hi = mm >> 3;
                float vv[8] = {rA[i][0].x, rA[i][0].y, rA[i][0].z, rA[i][0].w,
                               rA[i][1].x, rA[i][1].y, rA[i][1].z, rA[i][1].w};
                #pragma unroll
                for (int e2 = 0; e2 < 4; e2++) {
                    int k = kq*8 + e2*2;
                    int kc = k >> 4, kk = k & 15;
                    int khi = kk >> 3, tg2 = (kk >> 1) & 3;
                    int r = hi + 2*khi;
                    sA[buf][((kc*(2*NI) + mf)*32 + gg*4 + tg2)*4 + r] =
                        packh2(vv[e2*2], vv[e2*2+1]);
                }
            }
        }
        #pragma unroll
        for (int i = 0; i < 2; i++) {
            int f = t + i*256;
            int pq = f & 31;
            float cs[4] = {csv[i].x, csv[i].y, csv[i].z, csv[i].w};
            int k2 = f >> 5;
            float va[4] = {rB0[i].x, rB0[i].y, rB0[i].z, rB0[i].w};
            float vb[4] = {rB1[i].x, rB1[i].y, rB1[i].z, rB1[i].w};
            if (B2b) {
                va[0] -= rC0[i].x; va[1] -= rC0[i].y; va[2] -= rC0[i].z; va[3] -= rC0[i].w;
                vb[0] -= rC1[i].x; vb[1] -= rC1[i].y; vb[2] -= rC1[i].z; vb[3] -= rC1[i].w;
            }
            uint32_t* dst = &sB_[buf][k2*136 + pq*4];
            #pragma unroll
            for (int e = 0; e < 4; e++)
                dst[e] = packh2(va[e]*cs[e], vb[e]*cs[e]);
        }
    };
    __syncthreads();

    loadAB(0); storeAB(0, 0);
    __syncthreads();
    int cur = 0;
    for (int k0 = 0; k0 < Kd; k0 += 32) {
        int nk = k0 + 32;
        bool more = nk < Kd;
        if (more) loadAB(nk);
        #pragma unroll
        for (int kc = 0; kc < 2; kc++) {
            uint4 af[NI];
            #pragma unroll
            for (int i = 0; i < NI; i++)
                af[i] = ((const uint4*)sA[cur])[(kc*(2*NI) + warpM*NI + i)*32 + lane];
            uint32_t b0[4][2];
            #pragma unroll
            for (int j = 0; j < 4; j++) {
                int col = warpN*32 + j*8 + g;
                b0[j][0] = sB_[cur][(kc*8 + tg  )*136 + col];
                b0[j][1] = sB_[cur][(kc*8 + tg+4)*136 + col];
            }
            #pragma unroll
            for (int i = 0; i < NI; i++)
                #pragma unroll
                for (int j = 0; j < 4; j++)
                    MMA_F16(acc[i][j], af[i], b0[j]);
        }
        if (more) storeAB(nk, cur^1);
        __syncthreads();
        cur ^= 1;
    }

    #pragma unroll
    for (int i = 0; i < NI; i++) {
        int mlo = m0 + warpM*(NI*16) + i*16 + g;
        int mhi = mlo + 8;
        float blo = 0.f, bhi = 0.f;
        if (bias) {
            if (mlo < M) blo = bias[mlo];
            if (mhi < M) bhi = bias[mhi];
        }
        #pragma unroll
        for (int j = 0; j < 4; j++) {
            int p = p0 + warpN*32 + j*8 + 2*tg;
            float v00 = acc[i][j][0] + blo;
            float v01 = acc[i][j][1] + blo;
            float v10 = acc[i][j][2] + bhi;
            float v11 = acc[i][j][3] + bhi;
            if (mlo < M) { Ob[(size_t)mlo*P + p] = v00; Ob[(size_t)mlo*P + p + 1] = v01; }
            if (mhi < M) { Ob[(size_t)mhi*P + p] = v10; Ob[(size_t)mhi*P + p + 1] = v11; }
            if (OutT) {
                float* Tb = OutT + (size_t)bb*P*M;
                if (mlo < M) { Tb[(size_t)p*M + mlo] = v00; Tb[(size_t)(p+1)*M + mlo] = v01; }
                if (mhi < M) { Tb[(size_t)p*M + mhi] = v10; Tb[(size_t)(p+1)*M + mhi] = v11; }
            }
        }
    }
    if (statG) {
        float sg[NI], qg[NI];
        #pragma unroll
        for (int g2 = 0; g2 < NI; g2++) { sg[g2] = 0.f; qg[g2] = 0.f; }
        #pragma unroll
        for (int i = 0; i < NI; i++) {
            int grp = (warpM*NI + i) >> 1;
            int mlo = m0 + warpM*(NI*16) + i*16 + g;
            int mhi = mlo + 8;
            float blo = (bias && mlo < M) ? bias[mlo] : 0.f;
            float bhi = (bias && mhi < M) ? bias[mhi] : 0.f;
            #pragma unroll
            for (int j = 0; j < 4; j++) {
                float v00 = acc[i][j][0] + blo;
                float v01 = acc[i][j][1] + blo;
                float v10 = acc[i][j][2] + bhi;
                float v11 = acc[i][j][3] + bhi;
                if (mlo >= M) { v00 = 0.f; v01 = 0.f; }
                if (mhi >= M) { v10 = 0.f; v11 = 0.f; }
                sg[grp] += v00 + v01 + v10 + v11;
                qg[grp] += v00*v00 + v01*v01 + v10*v10 + v11*v11;
            }
        }
        const unsigned fm = 0xFFFFFFFFu;
        #pragma unroll
        for (int g2 = 0; g2 < NI; g2++) {
            sg[g2] += __shfl_xor_sync(fm, sg[g2], 1); sg[g2] += __shfl_xor_sync(fm, sg[g2], 2);
            qg[g2] += __shfl_xor_sync(fm, qg[g2], 1); qg[g2] += __shfl_xor_sync(fm, qg[g2], 2);
        }
        if (tg == 0) {
            #pragma unroll
            for (int g2 = 0; g2 < NI; g2++) {
                if (sg[g2] != 0.f || qg[g2] != 0.f) {
                    atomicAdd(&sS[g2], sg[g2]); atomicAdd(&sQ[g2], qg[g2]);
                }
            }
        }
        __syncthreads();
        if (t < NI && (m0/32 + t) < statG) {
            int bg = statOff + bb*statG + m0/32 + t;
            atomicAdd(&g_sum[0][bg], (double)sS[t]);
            atomicAdd(&g_sum[1][bg], (double)sQ[t]);
        }
    }
}

// ------------------------- group-norm statistics (fuse layer) ----------------
__global__ void stats_kernel(const float* __restrict__ in, long bStride, long gSize,
                             int G, int off)
{
    int bg = blockIdx.y;
    int b = bg / G, g = bg % G;
    const float* p = in + (size_t)b*bStride + (size_t)g*gSize;
    float s = 0.f, ss = 0.f;
    for (long i = (long)blockIdx.x*blockDim.x + threadIdx.x; i < gSize;
         i += (long)gridDim.x*blockDim.x) {
        float v = p[i];
        s += v; ss = fmaf(v, v, ss);
    }
    __shared__ double sh0[256], sh1[256];
    int t = threadIdx.x;
    sh0[t] = (double)s; sh1[t] = (double)ss;
    __syncthreads();
    for (int o = 128; o; o >>= 1) {
        if (t < o) { sh0[t] += sh0[t+o]; sh1[t] += sh1[t+o]; }
        __syncthreads();
    }
    if (t == 0) {
        atomicAdd(&g_sum[0][off + bg], sh0[0]);
        atomicAdd(&g_sum[1][off + bg], sh1[0]);
    }
}

__global__ void coeff_kernel(const float* __restrict__ gnw, const float* __restrict__ gnb,
                             int C, int Cg, double count, int off,
                             float* __restrict__ cA, float* __restrict__ cB)
{
    int i = blockIdx.x*blockDim.x + threadIdx.x;
    if (i >= BEFF*C) return;
    int b = i / C, ch = i % C;
    int G = C / Cg;
    int bg = off + b*G + ch/Cg;
    double mean = g_sum[0][bg] / count;
    double var  = g_sum[1][bg] / count - mean*mean;
    float rstd = (float)(1.0 / sqrt(var + 1e-5));
    float a = rstd * gnw[ch];
    cA[i] = a;
    cB[i] = gnb[ch] - (float)mean * a;
}

// ------------------------- feat from max/min ---------------------------------
__global__ void featmax_kernel(const float* __restrict__ mx, const float* __restrict__ mn,
                               const float* __restrict__ cA, const float* __restrict__ cB,
                               float* __restrict__ feat)
{
    int i = blockIdx.x*256 + threadIdx.x;
    if (i >= BEFF*192*NPTS) return;
    int b = i / (192*NPTS);
    int c = (i / NPTS) % 192;
    float a = cA[b*192+c];
    float base = (a > 0.f) ? mx[i] : mn[i];
    feat[i] = fmaxf(fmaf(a, base, cB[b*192+c]), 0.f);
}

// ------------------------- softmax + separate colsum -------------------------
__global__ void softmax_kernel(float* __restrict__ att)
{
    size_t row = blockIdx.x;
    float* p = att + row*NPTS;
    int t = threadIdx.x;
    float v[8];
    float mx = -1e30f;
    #pragma unroll
    for (int j = 0; j < 8; j++) { v[j] = p[t + j*256]; mx = fmaxf(mx, v[j]); }
    __shared__ float sh[256];
    sh[t] = mx; __syncthreads();
    for (int o = 128; o; o >>= 1) { if (t < o) sh[t] = fmaxf(sh[t], sh[t+o]); __syncthreads(); }
    mx = sh[0]; __syncthreads();
    float s = 0.f;
    #pragma unroll
    for (int j = 0; j < 8; j++) { v[j] = expf(v[j] - mx); s += v[j]; }
    sh[t] = s; __syncthreads();
    for (int o = 128; o; o >>= 1) { if (t < o) sh[t] += sh[t+o]; __syncthreads(); }
    float inv = 1.f / sh[0];
    #pragma unroll
    for (int j = 0; j < 8; j++) p[t + j*256] = v[j]*inv;
}

__global__ void colsum_kernel(const float* __restrict__ att, float* __restrict__ cs)
{
    int b = blockIdx.y;
    int m = blockIdx.x*256 + threadIdx.x;
    const float* p = att + (size_t)b*NPTS*NPTS + m;
    float s = 0.f;
    for (int n = 0; n < NPTS; n++) s += p[(size_t)n*NPTS];
    cs[b*NPTS + m] = s;
}

__global__ void update_kernel(const float* __restrict__ t_,
                              const float* __restrict__ cA, const float* __restrict__ cB,
                              float* __restrict__ feat, float* __restrict__ cat, int blk)
{
    size_t i = (size_t)blockIdx.x*256 + threadIdx.x;
    if (i >= (size_t)BEFF*192*NPTS) return;
    int b = (int)(i / (192*NPTS));
    int r = (int)(i % (192*NPTS));
    int c = r / NPTS, n = r % NPTS;
    float a = cA[b*192+c], bb = cB[b*192+c];
    float v = fmaxf(fmaf(a, t_[i], bb), 0.f);
    float x = feat[i] + v;
    feat[i] = x;
    cat[((size_t)b*768 + blk*192 + c)*NPTS + n] = x;
}

// ------------------------- final: gn + leaky + L2 normalize -----------------
__global__ void final_kernel(const float* __restrict__ fused,
                             const float* __restrict__ cA, const float* __restrict__ cB,
                             float* __restrict__ out)
{
    int b = blockIdx.y, n = blockIdx.x, t = threadIdx.x;
    float v[3]; float ss = 0.f;
    #pragma unroll
    for (int j = 0; j < 3; j++) {
        int c = t + j*256;
        float x = fused[((size_t)(b*768 + c))*NPTS + n];
        x = fmaf(cA[b*768+c], x, cB[b*768+c]);
        x = (x >= 0.f) ? x : 0.2f*x;
        v[j] = x; ss = fmaf(x, x, ss);
    }
    __shared__ float sh[256];
    sh[t] = ss; __syncthreads();
    for (int o = 128; o; o >>= 1) { if (t < o) sh[t] += sh[t+o]; __syncthreads(); }
    float inv = 1.f / (sqrtf(sh[0]) + 1e-8f);
    #pragma unroll
    for (int j = 0; j < 3; j++) {
        int c = t + j*256;
        out[((size_t)b*NPTS + n)*768 + c] = v[j]*inv;
    }
}

// ------------------------- host side ----------------------------------------
template<int NI>
static void launch_gemm(const float* W, long sW, const float* B, long sB,
                        const float* B2, const float* bias, const float* cs,
                        float* Out, long sOut, float* OutT,
                        int M, int Kd, int P, int statG, int statOff)
{
    dim3 grid(P/128, (M + NI*32 - 1)/(NI*32), BEFF);
    gemm_tc_kernel<NI><<<grid, 256>>>(W, sW, B, sB, B2, bias, cs,
                                      Out, sOut, OutT, M, Kd, P, statG, statOff);
}

extern "C" void kernel_launch(void* const* d_in, const int* in_sizes, int n_in,
                              void* d_out, int out_size)
{
    const float* src     = (const float*)d_in[0];
    const float* tgt     = (const float*)d_in[1];
    const float* lf_w0   = (const float*)d_in[5];
    const float* lf_gnw0 = (const float*)d_in[6];
    const float* lf_gnb0 = (const float*)d_in[7];
    const float* lf_w1   = (const float*)d_in[8];
    const float* lf_gnw1 = (const float*)d_in[9];
    const float* lf_gnb1 = (const float*)d_in[10];
    const float* lf_w2   = (const float*)d_in[11];
    const float* lf_gnw2 = (const float*)d_in[12];
    const float* lf_gnb2 = (const float*)d_in[13];
    const float* qk_w    = (const float*)d_in[14];
    const float* v_w     = (const float*)d_in[15];
    const float* v_b     = (const float*)d_in[16];
    const float* t_w     = (const float*)d_in[17];
    const float* t_b     = (const float*)d_in[18];
    const float* blk_gnw = (const float*)d_in[19];
    const float* blk_gnb = (const float*)d_in[20];
    const float* fuse_w  = (const float*)d_in[21];
    const float* fuse_gnw= (const float*)d_in[22];
    const float* fuse_gnb= (const float*)d_in[23];

    int*    pidx;   cudaGetSymbolAddress((void**)&pidx,   g_idx);
    __half* pact2;  cudaGetSymbolAddress((void**)&pact2,  g_act2h);
    float*  pmx;    cudaGetSymbolAddress((void**)&pmx,    g_mx);
    float*  pmn;    cudaGetSymbolAddress((void**)&pmn,    g_mn);
    float*  pW1f;   cudaGetSymbolAddress((void**)&pW1f,   g_W1f);
    float*  pqkw;   cudaGetSymbolAddress((void**)&pqkw,   g_qkw64);
    float*  pfeat;  cudaGetSymbolAddress((void**)&pfeat,  g_feat);
    float*  pq;     cudaGetSymbolAddress((void**)&pq,     g_q);
    float*  pqT;    cudaGetSymbolAddress((void**)&pqT,    g_qT);
    float*  pv;     cudaGetSymbolAddress((void**)&pv,     g_v);
    float*  patt;   cudaGetSymbolAddress((void**)&patt,   g_att);
    float*  pcs;    cudaGetSymbolAddress((void**)&pcs,    g_cs);
    float*  pxr;    cudaGetSymbolAddress((void**)&pxr,    g_xr);
    float*  pt;     cudaGetSymbolAddress((void**)&pt,     g_t);
    float*  pcat;   cudaGetSymbolAddress((void**)&pcat,   g_cat);
    float*  pfused; cudaGetSymbolAddress((void**)&pfused, g_fused);
    float*  pcA;    cudaGetSymbolAddress((void**)&pcA,    g_coefA);
    float*  pcB;    cudaGetSymbolAddress((void**)&pcB,    g_coefB);

    // 1) ball query + zero stats arena + pad all qk_w blocks
    ballq_kernel<<<dim3(NPTS/256, BEFF), 256>>>(src, tgt, pidx);
    zero_all_kernel<<<1, 256>>>();
    pad_qkw_kernel<<<(4*64*192 + 255)/256, 256>>>(qk_w);

    // 2) analytic GN1 -> folded W1f
    gram_kernel<<<dim3(64, BEFF), 256>>>(src, tgt, pidx);
    coeff1_kernel<<<BEFF, 128>>>(lf_w0, lf_gnw0, lf_gnb0, pW1f);

    // 3) layer2 fused GEMM (fp16 MMA) -> fp16 act2, GN2 stats fused
    layer2_kernel<<<dim3(PBIG/128, 2, BEFF), 256>>>(lf_w1, src, tgt, pidx, pW1f, pact2);
    coeff_kernel<<<(BEFF*256 + 255)/256, 256>>>(lf_gnw1, lf_gnb1, 256, 32,
                                                (double)(32L*PBIG), OFF_GN2, pcA, pcB);

    // 4) layer3 fused GEMM (fp16 MMA, 96-row tiles), max/min + GN3 stats
    layer3_kernel<<<dim3(PBIG/128, 2, BEFF), 256>>>(lf_w2, pact2, pcA, pcB, pmx, pmn);
    coeff_kernel<<<(BEFF*192 + 255)/256, 256>>>(lf_gnw2, lf_gnb2, 192, 32,
                                                (double)(32L*PBIG), OFF_GN3, pcA, pcB);

    // 5) feat = relu(gn3(max over K))
    featmax_kernel<<<(BEFF*192*NPTS + 255)/256, 256>>>(pmx, pmn, pcA, pcB, pfeat);

    // 6) four attention blocks
    for (int i = 0; i < 4; i++) {
        // q = qkw64 . feat  (M=64 incl. zero rows), fused qT epilogue (stride 64)
        launch_gemm<2>(pqkw + (size_t)i*64*192, 0L, pfeat, 192L*NPTS,
                       nullptr, nullptr, nullptr, pq, 64L*NPTS, pqT,
                       64, 192, NPTS, 0, 0);
        // v = v_w . feat + v_b (M=192)
        launch_gemm<3>(v_w + (size_t)i*192*192, 0L, pfeat, 192L*NPTS,
                       nullptr, v_b + i*192, nullptr, pv, 192L*NPTS, nullptr,
                       192, 192, NPTS, 0, 0);
        // att = qT . q  (fp16, Kd=64 padded)
        launch_gemm<4>(pqT, (long)NPTS*64, pq, 64L*NPTS,
                       nullptr, nullptr, nullptr, patt, (long)NPTS*NPTS, nullptr,
                       NPTS, 64, NPTS, 0, 0);
        softmax_kernel<<<BEFF*NPTS, 256>>>(patt);
        colsum_kernel<<<dim3(NPTS/256, BEFF), 256>>>(patt, pcs);
        // x_r = v . (att * 1/(1e-9+colsum))  — normalize-then-round
        launch_gemm<3>(pv, 192L*NPTS, patt, (long)NPTS*NPTS,
                       nullptr, nullptr, pcs, pxr, 192L*NPTS, nullptr,
                       192, NPTS, NPTS, 0, 0);
        // t = t_w . (feat - x_r) + t_b, GN stats fused
        launch_gemm<3>(t_w + (size_t)i*192*192, 0L, pfeat, 192L*NPTS,
                       pxr, t_b + i*192, nullptr, pt, 192L*NPTS, nullptr,
                       192, 192, NPTS, 6, OFF_BLK + i*64);
        coeff_kernel<<<(BEFF*192 + 255)/256, 256>>>(blk_gnw + i*192, blk_gnb + i*192,
                                                    192, 32, (double)(32L*NPTS),
                                                    OFF_BLK + i*64, pcA, pcB);
        update_kernel<<<(BEFF*192*NPTS + 255)/256, 256>>>(pt, pcA, pcB, pfeat, pcat, i);
    }

    // 7) fuse 768->768 (fp16 MMA)
    launch_gemm<4>(fuse_w, 0L, pcat, 768L*NPTS,
                   nullptr, nullptr, nullptr, pfused, 768L*NPTS, nullptr,
                   768, 768, NPTS, 0, 0);
    stats_kernel<<<dim3(64, BEFF*16), 256>>>(pfused, 768L*NPTS, 48L*NPTS, 16, OFF_FUSE);
    coeff_kernel<<<(BEFF*768 + 255)/256, 256>>>(fuse_gnw, fuse_gnb, 768, 48,
                                                (double)(48L*NPTS), OFF_FUSE, pcA, pcB);

    // 8) gn + leaky_relu + transpose + L2 normalize -> d_out
    final_kernel<<<dim3(NPTS, BEFF), 256>>>(pfused, pcA, pcB, (float*)d_out);
}

// round 17
// speedup vs baseline: 1.0784x; 1.0687x over previous
#include <cuda_runtime.h>
#include <cuda_fp16.h>
#include <math.h>
#include <float.h>
#include <stdint.h>

#define NPTS 2048
#define KNN 64
#define BEFF 4
#define PBIG (KNN*NPTS)   // 131072
#define R2 0.09f

// ------------------------- scratch (device globals; no allocs allowed) -------
__device__ int    g_idx[BEFF*NPTS*KNN];
__device__ __half g_act2h[(size_t)BEFF*256*PBIG];
__device__ float  g_mx[BEFF*192*NPTS];
__device__ float  g_mn[BEFF*192*NPTS];
__device__ float  g_feat[BEFF*192*NPTS];
__device__ float  g_q  [BEFF*64*NPTS];          // padded head dim 48->64
__device__ float  g_qT [BEFF*NPTS*64];
__device__ float  g_v  [BEFF*192*NPTS];
__device__ float  g_att[(size_t)BEFF*NPTS*NPTS];
__device__ float  g_cs [BEFF*NPTS];
__device__ float  g_xr [BEFF*192*NPTS];
__device__ float  g_t  [BEFF*192*NPTS];
__device__ float  g_cat[BEFF*768*NPTS];
__device__ float  g_fused[BEFF*768*NPTS];
__device__ double g_sum[2][512];
__device__ double g_gram[BEFF][28];
__device__ float  g_W1f[BEFF*128*8];
__device__ float  g_qkw64[4*64*192];
__device__ float  g_coefA[BEFF*768];
__device__ float  g_coefB[BEFF*768];

#define OFF_GN2   0
#define OFF_GN3   64
#define OFF_BLK   128
#define OFF_FUSE  384

__device__ __forceinline__ uint32_t packh2(float a, float b) {
    __half2 h = __floats2half2_rn(a, b);
    return *(uint32_t*)&h;
}
__device__ __forceinline__ float4 ld4(const float* p) { return *(const float4*)p; }
__device__ __forceinline__ float4 ld4(const __half* p) {
    uint2 u = *(const uint2*)p;
    __half2 h0 = *(__half2*)&u.x, h1 = *(__half2*)&u.y;
    float2 a = __half22float2(h0), b = __half22float2(h1);
    return make_float4(a.x, a.y, b.x, b.y);
}
__device__ __forceinline__ void st2(__half* p, float a, float b) {
    *(__half2*)p = __floats2half2_rn(a, b);
}

#define MMA_F16(d, a, b0v) \
    asm volatile( \
        "mma.sync.aligned.m16n8k16.row.col.f32.f16.f16.f32 " \
        "{%0,%1,%2,%3}, {%4,%5,%6,%7}, {%8,%9}, {%0,%1,%2,%3};\n" \
        : "+f"(d[0]), "+f"(d[1]), "+f"(d[2]), "+f"(d[3]) \
        : "r"(a.x), "r"(a.y), "r"(a.z), "r"(a.w), "r"(b0v[0]), "r"(b0v[1]))

// ------------------------- ball query ---------------------------------------
__global__ void ballq_kernel(const float* __restrict__ src,
                             const float* __restrict__ tgt,
                             int* __restrict__ idxout)
{
    int b = blockIdx.y;
    const float* xyz = (b < 2) ? src + (size_t)b*NPTS*3 : tgt + (size_t)(b-2)*NPTS*3;
    __shared__ float sx[NPTS], sy[NPTS], sz[NPTS], sq[NPTS];
    for (int i = threadIdx.x; i < NPTS; i += blockDim.x) {
        float x = xyz[i*3], y = xyz[i*3+1], z = xyz[i*3+2];
        sx[i] = x; sy[i] = y; sz[i] = z;
        sq[i] = x*x + y*y + z*z;
    }
    __syncthreads();
    int m = blockIdx.x*blockDim.x + threadIdx.x;
    float qx = sx[m], qy = sy[m], qz = sz[m], qs = sq[m];
    int* o = idxout + ((size_t)b*NPTS + m)*KNN;
    int cnt = 0;
    for (int j = 0; j < NPTS && cnt < KNN; j++) {
        float d = qs + sq[j] - 2.f*(qx*sx[j] + qy*sy[j] + qz*sz[j]);
        if (d <= R2) o[cnt++] = j;
    }
    int f0 = o[0];
    for (; cnt < KNN; cnt++) o[cnt] = f0;
}

// ------------------------- zero (gram + stats arena) -------------------------
__global__ void zero_all_kernel() {
    int t = threadIdx.x;
    for (int i = t; i < 1024; i += 256) ((double*)g_sum)[i] = 0.0;
    if (t < BEFF*28) ((double*)g_gram)[t] = 0.0;
}

// ------------------------- feature gram (analytic GN1 stats) -----------------
__global__ void gram_kernel(const float* __restrict__ src,
                            const float* __restrict__ tgt,
                            const int* __restrict__ idx)
{
    int b = blockIdx.y;
    const float* xyz = (b < 2) ? src + (size_t)b*NPTS*3 : tgt + (size_t)(b-2)*NPTS*3;
    float acc[27];
    #pragma unroll
    for (int i = 0; i < 27; i++) acc[i] = 0.f;
    for (int pos = blockIdx.x*256 + threadIdx.x; pos < PBIG; pos += 64*256) {
        int n = pos >> 6, k = pos & 63;
        int j = idx[((size_t)b*NPTS + n)*KNN + k];
        float f[6];
        f[0] = xyz[n*3]; f[1] = xyz[n*3+1]; f[2] = xyz[n*3+2];
        f[3] = xyz[j*3]   - f[0];
        f[4] = xyz[j*3+1] - f[1];
        f[5] = xyz[j*3+2] - f[2];
        #pragma unroll
        for (int i = 0; i < 6; i++) acc[i] += f[i];
        int c = 6;
        #pragma unroll
        for (int i = 0; i < 6; i++)
            #pragma unroll
            for (int jj = i; jj < 6; jj++)
                acc[c++] += f[i]*f[jj];
    }
    #pragma unroll
    for (int i = 0; i < 27; i++)
        #pragma unroll
        for (int o = 16; o; o >>= 1)
            acc[i] += __shfl_down_sync(0xFFFFFFFFu, acc[i], o);
    __shared__ float sh[8][27];
    int lane = threadIdx.x & 31, w = threadIdx.x >> 5;
    if (lane == 0)
        #pragma unroll
        for (int i = 0; i < 27; i++) sh[w][i] = acc[i];
    __syncthreads();
    if (threadIdx.x < 27) {
        double s = 0.0;
        for (int ww = 0; ww < 8; ww++) s += (double)sh[ww][threadIdx.x];
        atomicAdd(&g_gram[b][threadIdx.x], s);
    }
}

// ------------------------- coeff1: analytic GN1 -> folded W1f ---------------
__global__ void coeff1_kernel(const float* __restrict__ W1,
                              const float* __restrict__ gnw,
                              const float* __restrict__ gnb,
                              float* __restrict__ W1f)
{
    int b = blockIdx.x, c = threadIdx.x;
    double S[6], G[21];
    #pragma unroll
    for (int i = 0; i < 6; i++) S[i] = g_gram[b][i];
    #pragma unroll
    for (int i = 0; i < 21; i++) G[i] = g_gram[b][6+i];
    float w[6];
    #pragma unroll
    for (int i = 0; i < 6; i++) w[i] = W1[c*6+i];
    double s = 0.0, q = 0.0;
    #pragma unroll
    for (int i = 0; i < 6; i++) s += (double)w[i]*S[i];
    {
        int ci = 0;
        #pragma unroll
        for (int i = 0; i < 6; i++)
            #pragma unroll
            for (int j = i; j < 6; j++, ci++)
                q += (i==j ? 1.0 : 2.0) * (double)w[i]*(double)w[j]*G[ci];
    }
    double ss = s, qq = q;
    #pragma unroll
    for (int o = 16; o; o >>= 1) {
        ss += __shfl_down_sync(0xFFFFFFFFu, ss, o);
        qq += __shfl_down_sync(0xFFFFFFFFu, qq, o);
    }
    ss = __shfl_sync(0xFFFFFFFFu, ss, 0);
    qq = __shfl_sync(0xFFFFFFFFu, qq, 0);
    double count = 32.0 * (double)PBIG;
    double mean = ss / count;
    double var  = qq / count - mean*mean;
    float a  = gnw[c] * (float)(1.0 / sqrt(var + 1e-5));
    float b2 = gnb[c] - (float)mean * a;
    float* dst = W1f + ((size_t)b*128 + c)*8;
    #pragma unroll
    for (int i = 0; i < 6; i++) dst[i] = a*w[i];
    dst[6] = b2; dst[7] = 0.f;
}

// ------------------------- pad qk_w (all 4 blocks) 48x192 -> 64x192 ----------
__global__ void pad_qkw_kernel(const float* __restrict__ qkw)
{
    int i = blockIdx.x*256 + threadIdx.x;
    if (i >= 4*64*192) return;
    int blk = i / (64*192);
    int r = i % (64*192);
    int row = r / 192;
    g_qkw64[i] = (row < 48) ? qkw[(size_t)blk*48*192 + r] : 0.f;
}

// ------------------------- layer2 fused GEMM (fp16 MMA, BK=32) ---------------
__global__ void __launch_bounds__(256) layer2_kernel(
    const float* __restrict__ W,
    const float* __restrict__ src, const float* __restrict__ tgt,
    const int* __restrict__ idx,
    const float* __restrict__ W1f,
    __half* __restrict__ out)
{
    const int bb = blockIdx.z;
    const int m0 = blockIdx.y * 128;
    const int p0 = blockIdx.x * 128;
    const float* xyz = (bb < 2) ? src + (size_t)bb*NPTS*3 : tgt + (size_t)(bb-2)*NPTS*3;
    __half* Ob = out + (size_t)bb*256*PBIG;

    __shared__ uint32_t sA[2][2048];
    __shared__ uint32_t sB_[2][2176];
    __shared__ float sF[7*132];
    __shared__ float sW1[128*8];
    __shared__ float sS[4], sQ[4];

    const int t = threadIdx.x;
    const int lane = t & 31;
    const int w = t >> 5;
    const int warpM = w >> 2;
    const int warpN = w & 3;
    const int g  = lane >> 2;
    const int tg = lane & 3;

    for (int i = t; i < 128*8; i += 256) sW1[i] = W1f[(size_t)bb*128*8 + i];
    if (t < 128) {
        int col = t;
        int n = (p0 >> 6) + (col >> 6);
        int k = col & 63;
        int j = idx[((size_t)bb*NPTS + n)*KNN + k];
        float cx = xyz[n*3], cy = xyz[n*3+1], cz = xyz[n*3+2];
        sF[0*132+col] = cx; sF[1*132+col] = cy; sF[2*132+col] = cz;
        sF[3*132+col] = xyz[j*3]   - cx;
        sF[4*132+col] = xyz[j*3+1] - cy;
        sF[5*132+col] = xyz[j*3+2] - cz;
        sF[6*132+col] = 1.f;
    }
    if (t < 4) { sS[t] = 0.f; sQ[t] = 0.f; }

    float acc[4][4][4];
    #pragma unroll
    for (int i = 0; i < 4; i++)
        #pragma unroll
        for (int j = 0; j < 4; j++)
            #pragma unroll
            for (int r = 0; r < 4; r++) acc[i][j][r] = 0.f;

    float4 rA[2][2];
    auto loadA = [&](int k0) {
        #pragma unroll
        for (int i = 0; i < 2; i++) {
            int f = t*2 + i;
            int m = f >> 2, kq = f & 3;
            const float* sp = W + (size_t)(m0+m)*128 + k0 + kq*8;
            rA[i][0] = *(const float4*)sp;
            rA[i][1] = *(const float4*)(sp+4);
        }
    };
    auto storeA = [&](int buf) {
        #pragma unroll
        for (int i = 0; i < 2; i++) {
            int f = t*2 + i;
            int m = f >> 2, kq = f & 3;
            float vv[8] = {rA[i][0].x, rA[i][0].y, rA[i][0].z, rA[i][0].w,
                           rA[i][1].x, rA[i][1].y, rA[i][1].z, rA[i][1].w};
            int mf = m >> 4, mm = m & 15;
            int gg = mm & 7, hi = mm >> 3;
            #pragma unroll
            for (int e2 = 0; e2 < 4; e2++) {
                int k = kq*8 + e2*2;
                int kc = k >> 4, kk = k & 15;
                int khi = kk >> 3, tg2 = (kk >> 1) & 3;
                int r = hi + 2*khi;
                sA[buf][((kc*8 + mf)*32 + gg*4 + tg2)*4 + r] = packh2(vv[e2*2], vv[e2*2+1]);
            }
        }
    };
    auto computeB = [&](int k0, int buf) {
        #pragma unroll
        for (int i = 0; i < 2; i++) {
            int f = t + i*256;
            int k2 = f >> 5, pq = f & 31;
            const float* wa = &sW1[(k0 + 2*k2    )*8];
            const float* wb = &sW1[(k0 + 2*k2 + 1)*8];
            uint32_t* dst = &sB_[buf][k2*136 + pq*4];
            #pragma unroll
            for (int e = 0; e < 4; e++) {
                int c4 = pq*4 + e;
                float va = wa[6], vb = wb[6];
                #pragma unroll
                for (int ii = 0; ii < 6; ii++) {
                    float fv = sF[ii*132 + c4];
                    va = fmaf(wa[ii], fv, va);
                    vb = fmaf(wb[ii], fv, vb);
                }
                va = fmaxf(va, 0.f); vb = fmaxf(vb, 0.f);
                dst[e] = packh2(va, vb);
            }
        }
    };
    __syncthreads();

    loadA(0); storeA(0); computeB(0, 0);
    __syncthreads();
    int cur = 0;
    for (int k0 = 0; k0 < 128; k0 += 32) {
        int nk = k0 + 32;
        bool more = nk < 128;
        if (more) loadA(nk);
        #pragma unroll
        for (int kc = 0; kc < 2; kc++) {
            uint4 af[4];
            #pragma unroll
            for (int i = 0; i < 4; i++)
                af[i] = ((const uint4*)sA[cur])[(kc*8 + warpM*4 + i)*32 + lane];
            uint32_t b0[4][2];
            #pragma unroll
            for (int j = 0; j < 4; j++) {
                int col = warpN*32 + j*8 + g;
                b0[j][0] = sB_[cur][(kc*8 + tg  )*136 + col];
                b0[j][1] = sB_[cur][(kc*8 + tg+4)*136 + col];
            }
            #pragma unroll
            for (int i = 0; i < 4; i++)
                #pragma unroll
                for (int j = 0; j < 4; j++)
                    MMA_F16(acc[i][j], af[i], b0[j]);
        }
        if (more) { storeA(cur^1); computeB(nk, cur^1); }
        __syncthreads();
        cur ^= 1;
    }

    float s0 = 0.f, q0 = 0.f, s1 = 0.f, q1 = 0.f;
    #pragma unroll
    for (int i = 0; i < 4; i++) {
        int mlo = m0 + warpM*64 + i*16 + g;
        int mhi = mlo + 8;
        #pragma unroll
        for (int j = 0; j < 4; j++) {
            int p = p0 + warpN*32 + j*8 + 2*tg;
            st2(&Ob[(size_t)mlo*PBIG + p], acc[i][j][0], acc[i][j][1]);
            st2(&Ob[(size_t)mhi*PBIG + p], acc[i][j][2], acc[i][j][3]);
            #pragma unroll
            for (int r = 0; r < 4; r++) {
                float v = acc[i][j][r];
                if (i < 2) { s0 += v; q0 = fmaf(v, v, q0); }
                else       { s1 += v; q1 = fmaf(v, v, q1); }
            }
        }
    }
    const unsigned fm = 0xFFFFFFFFu;
    s0 += __shfl_xor_sync(fm, s0, 1); s0 += __shfl_xor_sync(fm, s0, 2);
    q0 += __shfl_xor_sync(fm, q0, 1); q0 += __shfl_xor_sync(fm, q0, 2);
    s1 += __shfl_xor_sync(fm, s1, 1); s1 += __shfl_xor_sync(fm, s1, 2);
    q1 += __shfl_xor_sync(fm, q1, 1); q1 += __shfl_xor_sync(fm, q1, 2);
    if (tg == 0) {
        atomicAdd(&sS[warpM*2+0], s0); atomicAdd(&sQ[warpM*2+0], q0);
        atomicAdd(&sS[warpM*2+1], s1); atomicAdd(&sQ[warpM*2+1], q1);
    }
    __syncthreads();
    if (t < 4) {
        int bg = OFF_GN2 + bb*8 + m0/32 + t;
        atomicAdd(&g_sum[0][bg], (double)sS[t]);
        atomicAdd(&g_sum[1][bg], (double)sQ[t]);
    }
}

// ------------------------- layer3 fused GEMM (fp16 MMA, 96-row tiles) --------
__global__ void __launch_bounds__(256) layer3_kernel(
    const float* __restrict__ W,
    const __half* __restrict__ act2,
    const float* __restrict__ cA2, const float* __restrict__ cB2,
    float* __restrict__ mxbuf, float* __restrict__ mnbuf)
{
    const int bb = blockIdx.z;
    const int m0 = blockIdx.y * 96;
    const int p0 = blockIdx.x * 128;
    const __half* Bb = act2 + (size_t)bb*256*PBIG;
    const float* cAb = cA2 + bb*256;
    const float* cBb = cB2 + bb*256;

    __shared__ uint32_t sA[2][1536];
    __shared__ uint32_t sB_[2][2176];
    __shared__ float sMx[2][96], sMn[2][96];
    __shared__ float sS[4], sQ[4];

    const int t = threadIdx.x;
    const int lane = t & 31;
    const int w = t >> 5;
    const int warpM = w >> 2;
    const int warpN = w & 3;
    const int g  = lane >> 2;
    const int tg = lane & 3;
    const int nh = warpN >> 1;

    if (t < 4) { sS[t] = 0.f; sQ[t] = 0.f; }

    float acc[3][4][4];
    #pragma unroll
    for (int i = 0; i < 3; i++)
        #pragma unroll
        for (int j = 0; j < 4; j++)
            #pragma unroll
            for (int r = 0; r < 4; r++) acc[i][j][r] = 0.f;

    float4 rA[2][2], rB0[2], rB1[2];
    auto loadAB = [&](int k0) {
        #pragma unroll
        for (int i = 0; i < 2; i++) {
            int f = t*2 + i;
            if (f < 384) {
                int m = f >> 2, kq = f & 3;
                const float* sp = W + (size_t)(m0+m)*256 + k0 + kq*8;
                rA[i][0] = *(const float4*)sp;
                rA[i][1] = *(const float4*)(sp+4);
            }
        }
        #pragma unroll
        for (int i = 0; i < 2; i++) {
            int f = t + i*256;
            int k2 = f >> 5, pq = f & 31;
            rB0[i] = ld4(Bb + (size_t)(k0 + 2*k2    )*PBIG + p0 + pq*4);
            rB1[i] = ld4(Bb + (size_t)(k0 + 2*k2 + 1)*PBIG + p0 + pq*4);
        }
    };
    auto storeAB = [&](int k0, int buf) {
        #pragma unroll
        for (int i = 0; i < 2; i++) {
            int f = t*2 + i;
            if (f < 384) {
                int m = f >> 2, kq = f & 3;
                float vv[8] = {rA[i][0].x, rA[i][0].y, rA[i][0].z, rA[i][0].w,
                               rA[i][1].x, rA[i][1].y, rA[i][1].z, rA[i][1].w};
                int mf = m >> 4, mm = m & 15;
                int gg = mm & 7, hi = mm >> 3;
                #pragma unroll
                for (int e2 = 0; e2 < 4; e2++) {
                    int k = kq*8 + e2*2;
                    int kc = k >> 4, kk = k & 15;
                    int khi = kk >> 3, tg2 = (kk >> 1) & 3;
                    int r = hi + 2*khi;
                    sA[buf][((kc*6 + mf)*32 + gg*4 + tg2)*4 + r] = packh2(vv[e2*2], vv[e2*2+1]);
                }
            }
        }
        #pragma unroll
        for (int i = 0; i < 2; i++) {
            int f = t + i*256;
            int k2 = f >> 5, pq = f & 31;
            int ka = k0 + 2*k2, kb = ka + 1;
            float aa = cAb[ka], ca = cBb[ka];
            float ab = cAb[kb], cb = cBb[kb];
            float va[4] = {rB0[i].x, rB0[i].y, rB0[i].z, rB0[i].w};
            float vb[4] = {rB1[i].x, rB1[i].y, rB1[i].z, rB1[i].w};
            uint32_t* dst = &sB_[buf][k2*136 + pq*4];
            #pragma unroll
            for (int e = 0; e < 4; e++) {
                float x = fmaxf(fmaf(aa, va[e], ca), 0.f);
                float y = fmaxf(fmaf(ab, vb[e], cb), 0.f);
                dst[e] = packh2(x, y);
            }
        }
    };

    loadAB(0); storeAB(0, 0);
    __syncthreads();
    int cur = 0;
    for (int k0 = 0; k0 < 256; k0 += 32) {
        int nk = k0 + 32;
        bool more = nk < 256;
        if (more) loadAB(nk);
        #pragma unroll
        for (int kc = 0; kc < 2; kc++) {
            uint4 af[3];
            #pragma unroll
            for (int i = 0; i < 3; i++)
                af[i] = ((const uint4*)sA[cur])[(kc*6 + warpM*3 + i)*32 + lane];
            uint32_t b0[4][2];
            #pragma unroll
            for (int j = 0; j < 4; j++) {
                int col = warpN*32 + j*8 + g;
                b0[j][0] = sB_[cur][(kc*8 + tg  )*136 + col];
                b0[j][1] = sB_[cur][(kc*8 + tg+4)*136 + col];
            }
            #pragma unroll
            for (int i = 0; i < 3; i++)
                #pragma unroll
                for (int j = 0; j < 4; j++)
                    MMA_F16(acc[i][j], af[i], b0[j]);
        }
        if (more) storeAB(nk, cur^1);
        __syncthreads();
        cur ^= 1;
    }

    const unsigned fm = 0xFFFFFFFFu;
    float sg[3] = {0.f,0.f,0.f}, qg[3] = {0.f,0.f,0.f};
    float rmx[6], rmn[6];
    #pragma unroll
    for (int i = 0; i < 3; i++) {
        int grp = (warpM*3 + i) >> 1;
        #pragma unroll
        for (int lh = 0; lh < 2; lh++) {
            float vmx = -FLT_MAX, vmn = FLT_MAX;
            #pragma unroll
            for (int j = 0; j < 4; j++) {
                float a = acc[i][j][lh*2], b2 = acc[i][j][lh*2+1];
                vmx = fmaxf(vmx, fmaxf(a, b2));
                vmn = fminf(vmn, fminf(a, b2));
                sg[grp] += a + b2;
                qg[grp] += a*a + b2*b2;
            }
            vmx = fmaxf(vmx, __shfl_xor_sync(fm, vmx, 1));
            vmx = fmaxf(vmx, __shfl_xor_sync(fm, vmx, 2));
            vmn = fminf(vmn, __shfl_xor_sync(fm, vmn, 1));
            vmn = fminf(vmn, __shfl_xor_sync(fm, vmn, 2));
            rmx[i*2+lh] = vmx; rmn[i*2+lh] = vmn;
        }
    }
    #pragma unroll
    for (int g2 = 0; g2 < 3; g2++) {
        sg[g2] += __shfl_xor_sync(fm, sg[g2], 1); sg[g2] += __shfl_xor_sync(fm, sg[g2], 2);
        qg[g2] += __shfl_xor_sync(fm, qg[g2], 1); qg[g2] += __shfl_xor_sync(fm, qg[g2], 2);
    }
    if (tg == 0) {
        #pragma unroll
        for (int g2 = 0; g2 < 3; g2++) {
            if (sg[g2] != 0.f || qg[g2] != 0.f) {
                atomicAdd(&sS[g2], sg[g2]); atomicAdd(&sQ[g2], qg[g2]);
            }
        }
        if ((warpN & 1) == 0) {
            #pragma unroll
            for (int i = 0; i < 3; i++)
                #pragma unroll
                for (int lh = 0; lh < 2; lh++) {
                    int mloc = warpM*48 + i*16 + g + lh*8;
                    sMx[nh][mloc] = rmx[i*2+lh];
                    sMn[nh][mloc] = rmn[i*2+lh];
                }
        }
    }
    __syncthreads();
    if (tg == 0 && (warpN & 1) == 1) {
        int n = (p0 >> 6) + nh;
        #pragma unroll
        for (int i = 0; i < 3; i++)
            #pragma unroll
            for (int lh = 0; lh < 2; lh++) {
                int mloc = warpM*48 + i*16 + g + lh*8;
                int m = m0 + mloc;
                float fx = fmaxf(rmx[i*2+lh], sMx[nh][mloc]);
                float fn = fminf(rmn[i*2+lh], sMn[nh][mloc]);
                size_t o = ((size_t)bb*192 + m)*NPTS + n;
                mxbuf[o] = fx; mnbuf[o] = fn;
            }
    }
    if (t < 3) {
        int bg = OFF_GN3 + bb*6 + m0/32 + t;
        atomicAdd(&g_sum[0][bg], (double)sS[t]);
        atomicAdd(&g_sum[1][bg], (double)sQ[t]);
    }
}

// ------------------------- generic fp16 GEMM (BK=32, Kd%32==0) ---------------
template<int NI>
__global__ void __launch_bounds__(256) gemm_tc_kernel(
    const float* __restrict__ W, long sW,
    const float* __restrict__ B, long sB,
    const float* __restrict__ B2,
    const float* __restrict__ bias,
    const float* __restrict__ colscale,
    float* __restrict__ Out, long sOut,
    float* __restrict__ OutT,
    int M, int Kd, int P, int statG, int statOff)
{
    const int bb = blockIdx.z;
    const int m0 = blockIdx.y * (NI*32);
    const int p0 = blockIdx.x * 128;
    const float* Wb  = W + (size_t)bb*sW;
    const float* Bb  = B + (size_t)bb*sB;
    const float* B2b = B2 ? B2 + (size_t)bb*sB : nullptr;
    float* Ob = Out + (size_t)bb*sOut;

    __shared__ uint32_t sA[2][512*NI];
    __shared__ uint32_t sB_[2][2176];
    __shared__ float sS[4], sQ[4];

    const int t = threadIdx.x;
    const int lane = t & 31;
    const int w = t >> 5;
    const int warpM = w >> 2;
    const int warpN = w & 3;
    const int g  = lane >> 2;
    const int tg = lane & 3;

    if (t < 4) { sS[t] = 0.f; sQ[t] = 0.f; }

    float acc[NI][4][4];
    #pragma unroll
    for (int i = 0; i < NI; i++)
        #pragma unroll
        for (int j = 0; j < 4; j++)
            #pragma unroll
            for (int r = 0; r < 4; r++) acc[i][j][r] = 0.f;

    float4 csv[2];
    #pragma unroll
    for (int i = 0; i < 2; i++) {
        if (colscale) {
            int pq = (t + i*256) & 31;
            float4 c = *(const float4*)(colscale + (size_t)bb*P + p0 + pq*4);
            csv[i] = make_float4(1.f/(1e-9f + c.x), 1.f/(1e-9f + c.y),
                                 1.f/(1e-9f + c.z), 1.f/(1e-9f + c.w));
        } else csv[i] = make_float4(1.f,1.f,1.f,1.f);
    }

    float4 rA[2][2], rB0[2], rB1[2], rC0[2], rC1[2];
    auto loadAB = [&](int k0) {
        #pragma unroll
        for (int i = 0; i < 2; i++) {
            int f = t*2 + i;
            if (f < 128*NI) {
                int m = f >> 2, kq = f & 3;
                int gm = m0 + m;
                if (gm < M) {
                    const float* sp = Wb + (size_t)gm*Kd + k0 + kq*8;
                    rA[i][0] = *(const float4*)sp;
                    rA[i][1] = *(const float4*)(sp+4);
                } else {
                    rA[i][0] = make_float4(0.f,0.f,0.f,0.f);
                    rA[i][1] = make_float4(0.f,0.f,0.f,0.f);
                }
            }
        }
        #pragma unroll
        for (int i = 0; i < 2; i++) {
            int f = t + i*256;
            int pq = f & 31;
            int k2 = f >> 5;
            size_t off0 = (size_t)(k0 + 2*k2)*P + p0 + pq*4;
            rB0[i] = *(const float4*)(Bb + off0);
            rB1[i] = *(const float4*)(Bb + off0 + P);
            if (B2b) {
                rC0[i] = *(const float4*)(B2b + off0);
                rC1[i] = *(const float4*)(B2b + off0 + P);
            }
        }
    };
    auto storeAB = [&](int k0, int buf) {
        #pragma unroll
        for (int i = 0; i < 2; i++) {
            int f = t*2 + i;
            if (f < 128*NI) {
                int m = f >> 2, kq = f & 3;
                int mf = m >> 4, mm = m & 15;
                int gg = mm & 7, hi = mm >> 3;
                float vv[8] = {rA[i][0].x, rA[i][0].y, rA[i][0].z, rA[i][0].w,
                               rA[i][1].x, rA[i][1].y, rA[i][1].z, rA[i][1].w};
                #pragma unroll
                for (int e2 = 0; e2 < 4; e2++) {
                    int k = kq*8 + e2*2;
                    int kc = k >> 4, kk = k & 15;
                    int khi = kk >> 3, tg2 = (kk >> 1) & 3;
                    int r = hi + 2*khi;
                    sA[buf][((kc*(2*NI) + mf)*32 + gg*4 + tg2)*4 + r] =
                        packh2(vv[e2*2], vv[e2*2+1]);
                }
            }
        }
        #pragma unroll
        for (int i = 0; i < 2; i++) {
            int f = t + i*256;
            int pq = f & 31;
            float cs[4] = {csv[i].x, csv[i].y, csv[i].z, csv[i].w};
            int k2 = f >> 5;
            float va[4] = {rB0[i].x, rB0[i].y, rB0[i].z, rB0[i].w};
            float vb[4] = {rB1[i].x, rB1[i].y, rB1[i].z, rB1[i].w};
            if (B2b) {
                va[0] -= rC0[i].x; va[1] -= rC0[i].y; va[2] -= rC0[i].z; va[3] -= rC0[i].w;
                vb[0] -= rC1[i].x; vb[1] -= rC1[i].y; vb[2] -= rC1[i].z; vb[3] -= rC1[i].w;
            }
            uint32_t* dst = &sB_[buf][k2*136 + pq*4];
            #pragma unroll
            for (int e = 0; e < 4; e++)
                dst[e] = packh2(va[e]*cs[e], vb[e]*cs[e]);
        }
    };
    __syncthreads();

    loadAB(0); storeAB(0, 0);
    __syncthreads();
    int cur = 0;
    for (int k0 = 0; k0 < Kd; k0 += 32) {
        int nk = k0 + 32;
        bool more = nk < Kd;
        if (more) loadAB(nk);
        #pragma unroll
        for (int kc = 0; kc < 2; kc++) {
            uint4 af[NI];
            #pragma unroll
            for (int i = 0; i < NI; i++)
                af[i] = ((const uint4*)sA[cur])[(kc*(2*NI) + warpM*NI + i)*32 + lane];
            uint32_t b0[4][2];
            #pragma unroll
            for (int j = 0; j < 4; j++) {
                int col = warpN*32 + j*8 + g;
                b0[j][0] = sB_[cur][(kc*8 + tg  )*136 + col];
                b0[j][1] = sB_[cur][(kc*8 + tg+4)*136 + col];
            }
            #pragma unroll
            for (int i = 0; i < NI; i++)
                #pragma unroll
                for (int j = 0; j < 4; j++)
                    MMA_F16(acc[i][j], af[i], b0[j]);
        }
        if (more) storeAB(nk, cur^1);
        __syncthreads();
        cur ^= 1;
    }

    #pragma unroll
    for (int i = 0; i < NI; i++) {
        int mlo = m0 + warpM*(NI*16) + i*16 + g;
        int mhi = mlo + 8;
        float blo = 0.f, bhi = 0.f;
        if (bias) {
            if (mlo < M) blo = bias[mlo];
            if (mhi < M) bhi = bias[mhi];
        }
        #pragma unroll
        for (int j = 0; j < 4; j++) {
            int p = p0 + warpN*32 + j*8 + 2*tg;
            float v00 = acc[i][j][0] + blo;
            float v01 = acc[i][j][1] + blo;
            float v10 = acc[i][j][2] + bhi;
            float v11 = acc[i][j][3] + bhi;
            if (mlo < M) { Ob[(size_t)mlo*P + p] = v00; Ob[(size_t)mlo*P + p + 1] = v01; }
            if (mhi < M) { Ob[(size_t)mhi*P + p] = v10; Ob[(size_t)mhi*P + p + 1] = v11; }
            if (OutT) {
                float* Tb = OutT + (size_t)bb*P*M;
                if (mlo < M) { Tb[(size_t)p*M + mlo] = v00; Tb[(size_t)(p+1)*M + mlo] = v01; }
                if (mhi < M) { Tb[(size_t)p*M + mhi] = v10; Tb[(size_t)(p+1)*M + mhi] = v11; }
            }
        }
    }
    if (statG) {
        float sg[NI], qg[NI];
        #pragma unroll
        for (int g2 = 0; g2 < NI; g2++) { sg[g2] = 0.f; qg[g2] = 0.f; }
        #pragma unroll
        for (int i = 0; i < NI; i++) {
            int grp = (warpM*NI + i) >> 1;
            int mlo = m0 + warpM*(NI*16) + i*16 + g;
            int mhi = mlo + 8;
            float blo = (bias && mlo < M) ? bias[mlo] : 0.f;
            float bhi = (bias && mhi < M) ? bias[mhi] : 0.f;
            #pragma unroll
            for (int j = 0; j < 4; j++) {
                float v00 = acc[i][j][0] + blo;
                float v01 = acc[i][j][1] + blo;
                float v10 = acc[i][j][2] + bhi;
                float v11 = acc[i][j][3] + bhi;
                if (mlo >= M) { v00 = 0.f; v01 = 0.f; }
                if (mhi >= M) { v10 = 0.f; v11 = 0.f; }
                sg[grp] += v00 + v01 + v10 + v11;
                qg[grp] += v00*v00 + v01*v01 + v10*v10 + v11*v11;
            }
        }
        const unsigned fm = 0xFFFFFFFFu;
        #pragma unroll
        for (int g2 = 0; g2 < NI; g2++) {
            sg[g2] += __shfl_xor_sync(fm, sg[g2], 1); sg[g2] += __shfl_xor_sync(fm, sg[g2], 2);
            qg[g2] += __shfl_xor_sync(fm, qg[g2], 1); qg[g2] += __shfl_xor_sync(fm, qg[g2], 2);
        }
        if (tg == 0) {
            #pragma unroll
            for (int g2 = 0; g2 < NI; g2++) {
                if (sg[g2] != 0.f || qg[g2] != 0.f) {
                    atomicAdd(&sS[g2], sg[g2]); atomicAdd(&sQ[g2], qg[g2]);
                }
            }
        }
        __syncthreads();
        if (t < NI && (m0/32 + t) < statG) {
            int bg = statOff + bb*statG + m0/32 + t;
            atomicAdd(&g_sum[0][bg], (double)sS[t]);
            atomicAdd(&g_sum[1][bg], (double)sQ[t]);
        }
    }
}

// ------------------------- group-norm statistics (fuse layer) ----------------
__global__ void stats_kernel(const float* __restrict__ in, long bStride, long gSize,
                             int G, int off)
{
    int bg = blockIdx.y;
    int b = bg / G, g = bg % G;
    const float* p = in + (size_t)b*bStride + (size_t)g*gSize;
    float s = 0.f, ss = 0.f;
    for (long i = (long)blockIdx.x*blockDim.x + threadIdx.x; i < gSize;
         i += (long)gridDim.x*blockDim.x) {
        float v = p[i];
        s += v; ss = fmaf(v, v, ss);
    }
    __shared__ double sh0[256], sh1[256];
    int t = threadIdx.x;
    sh0[t] = (double)s; sh1[t] = (double)ss;
    __syncthreads();
    for (int o = 128; o; o >>= 1) {
        if (t < o) { sh0[t] += sh0[t+o]; sh1[t] += sh1[t+o]; }
        __syncthreads();
    }
    if (t == 0) {
        atomicAdd(&g_sum[0][off + bg], sh0[0]);
        atomicAdd(&g_sum[1][off + bg], sh1[0]);
    }
}

__global__ void coeff_kernel(const float* __restrict__ gnw, const float* __restrict__ gnb,
                             int C, int Cg, double count, int off,
                             float* __restrict__ cA, float* __restrict__ cB)
{
    int i = blockIdx.x*blockDim.x + threadIdx.x;
    if (i >= BEFF*C) return;
    int b = i / C, ch = i % C;
    int G = C / Cg;
    int bg = off + b*G + ch/Cg;
    double mean = g_sum[0][bg] / count;
    double var  = g_sum[1][bg] / count - mean*mean;
    float rstd = (float)(1.0 / sqrt(var + 1e-5));
    float a = rstd * gnw[ch];
    cA[i] = a;
    cB[i] = gnb[ch] - (float)mean * a;
}

// ------------------------- feat from max/min ---------------------------------
__global__ void featmax_kernel(const float* __restrict__ mx, const float* __restrict__ mn,
                               const float* __restrict__ cA, const float* __restrict__ cB,
                               float* __restrict__ feat)
{
    int i = blockIdx.x*256 + threadIdx.x;
    if (i >= BEFF*192*NPTS) return;
    int b = i / (192*NPTS);
    int c = (i / NPTS) % 192;
    float a = cA[b*192+c];
    float base = (a > 0.f) ? mx[i] : mn[i];
    feat[i] = fmaxf(fmaf(a, base, cB[b*192+c]), 0.f);
}

// ------------------------- softmax (zeros cs[row], shuffle reductions) -------
__global__ void softmax_kernel(float* __restrict__ att, float* __restrict__ cs)
{
    size_t row = blockIdx.x;
    float* p = att + row*NPTS;
    int t = threadIdx.x;
    if (t == 0) cs[row] = 0.f;   // 1:1 map: 8192 blocks, 8192 cs entries
    const unsigned fm = 0xFFFFFFFFu;
    int lane = t & 31, wp = t >> 5;
    __shared__ float sh[8];

    float v[8];
    float mx = -1e30f;
    #pragma unroll
    for (int j = 0; j < 8; j++) { v[j] = p[t + j*256]; mx = fmaxf(mx, v[j]); }
    #pragma unroll
    for (int o = 16; o; o >>= 1) mx = fmaxf(mx, __shfl_xor_sync(fm, mx, o));
    if (lane == 0) sh[wp] = mx;
    __syncthreads();
    mx = sh[0];
    #pragma unroll
    for (int ww = 1; ww < 8; ww++) mx = fmaxf(mx, sh[ww]);
    __syncthreads();

    float s = 0.f;
    #pragma unroll
    for (int j = 0; j < 8; j++) { v[j] = expf(v[j] - mx); s += v[j]; }
    #pragma unroll
    for (int o = 16; o; o >>= 1) s += __shfl_xor_sync(fm, s, o);
    if (lane == 0) sh[wp] = s;
    __syncthreads();
    s = sh[0];
    #pragma unroll
    for (int ww = 1; ww < 8; ww++) s += sh[ww];
    float inv = 1.f / s;
    #pragma unroll
    for (int j = 0; j < 8; j++) p[t + j*256] = v[j]*inv;
}

// ------------------------- colsum: 8 n-chunks, MLP-8 unroll, atomics ----------
__global__ void colsum_kernel(const float* __restrict__ att, float* __restrict__ cs)
{
    int b = blockIdx.z;
    int n0 = blockIdx.y * 256;
    int m = blockIdx.x*256 + threadIdx.x;
    const float* p = att + (size_t)b*NPTS*NPTS + (size_t)n0*NPTS + m;
    float a0 = 0.f, a1 = 0.f, a2 = 0.f, a3 = 0.f;
    float a4 = 0.f, a5 = 0.f, a6 = 0.f, a7 = 0.f;
    #pragma unroll 4
    for (int n = 0; n < 256; n += 8) {
        a0 += p[(size_t)(n+0)*NPTS];
        a1 += p[(size_t)(n+1)*NPTS];
        a2 += p[(size_t)(n+2)*NPTS];
        a3 += p[(size_t)(n+3)*NPTS];
        a4 += p[(size_t)(n+4)*NPTS];
        a5 += p[(size_t)(n+5)*NPTS];
        a6 += p[(size_t)(n+6)*NPTS];
        a7 += p[(size_t)(n+7)*NPTS];
    }
    float s = ((a0 + a1) + (a2 + a3)) + ((a4 + a5) + (a6 + a7));
    atomicAdd(&cs[b*NPTS + m], s);
}

__global__ void update_kernel(const float* __restrict__ t_,
                              const float* __restrict__ cA, const float* __restrict__ cB,
                              float* __restrict__ feat, float* __restrict__ cat, int blk)
{
    size_t i = (size_t)blockIdx.x*256 + threadIdx.x;
    if (i >= (size_t)BEFF*192*NPTS) return;
    int b = (int)(i / (192*NPTS));
    int r = (int)(i % (192*NPTS));
    int c = r / NPTS, n = r % NPTS;
    float a = cA[b*192+c], bb = cB[b*192+c];
    float v = fmaxf(fmaf(a, t_[i], bb), 0.f);
    float x = feat[i] + v;
    feat[i] = x;
    cat[((size_t)b*768 + blk*192 + c)*NPTS + n] = x;
}

// ------------------------- final: gn + leaky + L2 normalize -----------------
__global__ void final_kernel(const float* __restrict__ fused,
                             const float* __restrict__ cA, const float* __restrict__ cB,
                             float* __restrict__ out)
{
    int b = blockIdx.y, n = blockIdx.x, t = threadIdx.x;
    float v[3]; float ss = 0.f;
    #pragma unroll
    for (int j = 0; j < 3; j++) {
        int c = t + j*256;
        float x = fused[((size_t)(b*768 + c))*NPTS + n];
        x = fmaf(cA[b*768+c], x, cB[b*768+c]);
        x = (x >= 0.f) ? x : 0.2f*x;
        v[j] = x; ss = fmaf(x, x, ss);
    }
    __shared__ float sh[256];
    sh[t] = ss; __syncthreads();
    for (int o = 128; o; o >>= 1) { if (t < o) sh[t] += sh[t+o]; __syncthreads(); }
    float inv = 1.f / (sqrtf(sh[0]) + 1e-8f);
    #pragma unroll
    for (int j = 0; j < 3; j++) {
        int c = t + j*256;
        out[((size_t)b*NPTS + n)*768 + c] = v[j]*inv;
    }
}

// ------------------------- host side ----------------------------------------
template<int NI>
static void launch_gemm(const float* W, long sW, const float* B, long sB,
                        const float* B2, const float* bias, const float* cs,
                        float* Out, long sOut, float* OutT,
                        int M, int Kd, int P, int statG, int statOff)
{
    dim3 grid(P/128, (M + NI*32 - 1)/(NI*32), BEFF);
    gemm_tc_kernel<NI><<<grid, 256>>>(W, sW, B, sB, B2, bias, cs,
                                      Out, sOut, OutT, M, Kd, P, statG, statOff);
}

extern "C" void kernel_launch(void* const* d_in, const int* in_sizes, int n_in,
                              void* d_out, int out_size)
{
    const float* src     = (const float*)d_in[0];
    const float* tgt     = (const float*)d_in[1];
    const float* lf_w0   = (const float*)d_in[5];
    const float* lf_gnw0 = (const float*)d_in[6];
    const float* lf_gnb0 = (const float*)d_in[7];
    const float* lf_w1   = (const float*)d_in[8];
    const float* lf_gnw1 = (const float*)d_in[9];
    const float* lf_gnb1 = (const float*)d_in[10];
    const float* lf_w2   = (const float*)d_in[11];
    const float* lf_gnw2 = (const float*)d_in[12];
    const float* lf_gnb2 = (const float*)d_in[13];
    const float* qk_w    = (const float*)d_in[14];
    const float* v_w     = (const float*)d_in[15];
    const float* v_b     = (const float*)d_in[16];
    const float* t_w     = (const float*)d_in[17];
    const float* t_b     = (const float*)d_in[18];
    const float* blk_gnw = (const float*)d_in[19];
    const float* blk_gnb = (const float*)d_in[20];
    const float* fuse_w  = (const float*)d_in[21];
    const float* fuse_gnw= (const float*)d_in[22];
    const float* fuse_gnb= (const float*)d_in[23];

    int*    pidx;   cudaGetSymbolAddress((void**)&pidx,   g_idx);
    __half* pact2;  cudaGetSymbolAddress((void**)&pact2,  g_act2h);
    float*  pmx;    cudaGetSymbolAddress((void**)&pmx,    g_mx);
    float*  pmn;    cudaGetSymbolAddress((void**)&pmn,    g_mn);
    float*  pW1f;   cudaGetSymbolAddress((void**)&pW1f,   g_W1f);
    float*  pqkw;   cudaGetSymbolAddress((void**)&pqkw,   g_qkw64);
    float*  pfeat;  cudaGetSymbolAddress((void**)&pfeat,  g_feat);
    float*  pq;     cudaGetSymbolAddress((void**)&pq,     g_q);
    float*  pqT;    cudaGetSymbolAddress((void**)&pqT,    g_qT);
    float*  pv;     cudaGetSymbolAddress((void**)&pv,     g_v);
    float*  patt;   cudaGetSymbolAddress((void**)&patt,   g_att);
    float*  pcs;    cudaGetSymbolAddress((void**)&pcs,    g_cs);
    float*  pxr;    cudaGetSymbolAddress((void**)&pxr,    g_xr);
    float*  pt;     cudaGetSymbolAddress((void**)&pt,     g_t);
    float*  pcat;   cudaGetSymbolAddress((void**)&pcat,   g_cat);
    float*  pfused; cudaGetSymbolAddress((void**)&pfused, g_fused);
    float*  pcA;    cudaGetSymbolAddress((void**)&pcA,    g_coefA);
    float*  pcB;    cudaGetSymbolAddress((void**)&pcB,    g_coefB);

    // 1) ball query + zero stats arena + pad all qk_w blocks
    ballq_kernel<<<dim3(NPTS/256, BEFF), 256>>>(src, tgt, pidx);
    zero_all_kernel<<<1, 256>>>();
    pad_qkw_kernel<<<(4*64*192 + 255)/256, 256>>>(qk_w);

    // 2) analytic GN1 -> folded W1f
    gram_kernel<<<dim3(64, BEFF), 256>>>(src, tgt, pidx);
    coeff1_kernel<<<BEFF, 128>>>(lf_w0, lf_gnw0, lf_gnb0, pW1f);

    // 3) layer2 fused GEMM (fp16 MMA) -> fp16 act2, GN2 stats fused
    layer2_kernel<<<dim3(PBIG/128, 2, BEFF), 256>>>(lf_w1, src, tgt, pidx, pW1f, pact2);
    coeff_kernel<<<(BEFF*256 + 255)/256, 256>>>(lf_gnw1, lf_gnb1, 256, 32,
                                                (double)(32L*PBIG), OFF_GN2, pcA, pcB);

    // 4) layer3 fused GEMM (fp16 MMA, 96-row tiles), max/min + GN3 stats
    layer3_kernel<<<dim3(PBIG/128, 2, BEFF), 256>>>(lf_w2, pact2, pcA, pcB, pmx, pmn);
    coeff_kernel<<<(BEFF*192 + 255)/256, 256>>>(lf_gnw2, lf_gnb2, 192, 32,
                                                (double)(32L*PBIG), OFF_GN3, pcA, pcB);

    // 5) feat = relu(gn3(max over K))
    featmax_kernel<<<(BEFF*192*NPTS + 255)/256, 256>>>(pmx, pmn, pcA, pcB, pfeat);

    // 6) four attention blocks
    for (int i = 0; i < 4; i++) {
        // q = qkw64 . feat  (M=64 incl. zero rows), fused qT epilogue (stride 64)
        launch_gemm<2>(pqkw + (size_t)i*64*192, 0L, pfeat, 192L*NPTS,
                       nullptr, nullptr, nullptr, pq, 64L*NPTS, pqT,
                       64, 192, NPTS, 0, 0);
        // v = v_w . feat + v_b (M=192)
        launch_gemm<3>(v_w + (size_t)i*192*192, 0L, pfeat, 192L*NPTS,
                       nullptr, v_b + i*192, nullptr, pv, 192L*NPTS, nullptr,
                       192, 192, NPTS, 0, 0);
        // att = qT . q  (fp16, Kd=64 padded)
        launch_gemm<4>(pqT, (long)NPTS*64, pq, 64L*NPTS,
                       nullptr, nullptr, nullptr, patt, (long)NPTS*NPTS, nullptr,
                       NPTS, 64, NPTS, 0, 0);
        // softmax (also zeroes cs), then parallel colsum (atomics, 8 adds/addr)
        softmax_kernel<<<BEFF*NPTS, 256>>>(patt, pcs);
        colsum_kernel<<<dim3(NPTS/256, 8, BEFF), 256>>>(patt, pcs);
        // x_r = v . (att * 1/(1e-9+colsum))  — normalize-then-round
        launch_gemm<3>(pv, 192L*NPTS, patt, (long)NPTS*NPTS,
                       nullptr, nullptr, pcs, pxr, 192L*NPTS, nullptr,
                       192, NPTS, NPTS, 0, 0);
        // t = t_w . (feat - x_r) + t_b, GN stats fused
        launch_gemm<3>(t_w + (size_t)i*192*192, 0L, pfeat, 192L*NPTS,
                       pxr, t_b + i*192, nullptr, pt, 192L*NPTS, nullptr,
                       192, 192, NPTS, 6, OFF_BLK + i*64);
        coeff_kernel<<<(BEFF*192 + 255)/256, 256>>>(blk_gnw + i*192, blk_gnb + i*192,
                                                    192, 32, (double)(32L*NPTS),
                                                    OFF_BLK + i*64, pcA, pcB);
        update_kernel<<<(BEFF*192*NPTS + 255)/256, 256>>>(pt, pcA, pcB, pfeat, pcat, i);
    }

    // 7) fuse 768->768 (fp16 MMA)
    launch_gemm<4>(fuse_w, 0L, pcat, 768L*NPTS,
                   nullptr, nullptr, nullptr, pfused, 768L*NPTS, nullptr,
                   768, 768, NPTS, 0, 0);
    stats_kernel<<<dim3(64, BEFF*16), 256>>>(pfused, 768L*NPTS, 48L*NPTS, 16, OFF_FUSE);
    coeff_kernel<<<(BEFF*768 + 255)/256, 256>>>(fuse_gnw, fuse_gnb, 768, 48,
                                                (double)(48L*NPTS), OFF_FUSE, pcA, pcB);

    // 8) gn + leaky_relu + transpose + L2 normalize -> d_out
    final_kernel<<<dim3(NPTS, BEFF), 256>>>(pfused, pcA, pcB, (float*)d_out);
}